// round 15
// baseline (speedup 1.0000x reference)
#include <cuda_runtime.h>
#include <cuda_fp16.h>
#include <math.h>
#include <stdint.h>
#define NA 4096
#define NB 8192
#define FDIM 133
#define BFDIM 147
#define HD 256
#define NMOL 64
#define MAXNB 6
#define KP_WI 160
#define KP_WO 416
#define N3 399
#define LOSCL 2048.0f
#define INVLO (1.0f/2048.0f)
#define PSCL 1024.0f
typedef __half f16;

__device__ __align__(16) float g_W3[FDIM*N3];
__device__ __align__(16) float g_qkv[NA*N3];
__device__ __align__(16) float g_fe[NA*FDIM];
__device__ __align__(16) float g_inputs[NB*HD];
__device__ __align__(16) float g_msg[NB*HD];
__device__ __align__(16) float g_amsg[NA*HD];
__device__ __align__(16) float g_dmpnn[NB*HD];
__device__ __align__(16) float g_attm[NB*HD];
__device__ __align__(16) float g_atomh[NA*HD];
__device__ __align__(16) float g_hmwa[NA*HD];
__device__ __align__(16) float g_Opart[2*NB*HD];
__device__ __align__(16) float g_lpart[2*NB];
__device__ __align__(16) float g_mpart[2*NB];
__device__ __align__(16) f16 g_Q16[NB*HD];
__device__ __align__(16) f16 g_K16[NB*HD];
__device__ __align__(16) f16 g_V16[NB*HD];
__device__ __align__(16) f16 g_msghi[NB*HD];
__device__ __align__(16) f16 g_msglo[NB*HD];
__device__ __align__(16) f16 g_tmphi[NB*HD];
__device__ __align__(16) f16 g_tmplo[NB*HD];
__device__ __align__(16) f16 g_avhi[NB*HD];
__device__ __align__(16) f16 g_avlo[NB*HD];
__device__ __align__(16) f16 g_fbhi[NB*KP_WI];
__device__ __align__(16) f16 g_fblo[NB*KP_WI];
__device__ __align__(16) f16 g_cathi[NA*KP_WO];
__device__ __align__(16) f16 g_catlo[NA*KP_WO];
__device__ __align__(16) f16 g_ahhi[NA*HD];
__device__ __align__(16) f16 g_ahlo[NA*HD];
__device__ __align__(16) f16 g_Withi[HD*KP_WI];
__device__ __align__(16) f16 g_Witlo[HD*KP_WI];
__device__ __align__(16) f16 g_Whthi[HD*HD];
__device__ __align__(16) f16 g_Whtlo[HD*HD];
__device__ __align__(16) f16 g_Wqkvthi[3*HD*HD];
__device__ __align__(16) f16 g_Wqkvtlo[3*HD*HD];
__device__ __align__(16) f16 g_Wathi[HD*HD];
__device__ __align__(16) f16 g_Watlo[HD*HD];
__device__ __align__(16) f16 g_Wothi[HD*KP_WO];
__device__ __align__(16) f16 g_Wotlo[HD*KP_WO];

__device__ __forceinline__ void mma_f16(float* c,uint32_t a0,uint32_t a1,uint32_t a2,uint32_t a3,uint32_t b0,uint32_t b1){
    asm("mma.sync.aligned.m16n8k16.row.col.f32.f16.f16.f32 {%0,%1,%2,%3},{%4,%5,%6,%7},{%8,%9},{%0,%1,%2,%3};\n"
        :"+f"(c[0]),"+f"(c[1]),"+f"(c[2]),"+f"(c[3]):"r"(a0),"r"(a1),"r"(a2),"r"(a3),"r"(b0),"r"(b1));
}
__device__ __forceinline__ uint32_t smaddr(const void* p){return (uint32_t)__cvta_generic_to_shared(p);}
__device__ __forceinline__ void ldsm4(uint32_t* r,uint32_t a){
    asm volatile("ldmatrix.sync.aligned.m8n8.x4.shared.b16 {%0,%1,%2,%3},[%4];":"=r"(r[0]),"=r"(r[1]),"=r"(r[2]),"=r"(r[3]):"r"(a));
}
__device__ __forceinline__ void ldsm4t(uint32_t* r,uint32_t a){
    asm volatile("ldmatrix.sync.aligned.m8n8.x4.trans.shared.b16 {%0,%1,%2,%3},[%4];":"=r"(r[0]),"=r"(r[1]),"=r"(r[2]),"=r"(r[3]):"r"(a));
}
__device__ __forceinline__ void cpa16(uint32_t s,const void* g){
    asm volatile("cp.async.ca.shared.global [%0],[%1],16;\n"::"r"(s),"l"(g));
}
#define CP_COMMIT() asm volatile("cp.async.commit_group;\n":::"memory")
#define CP_WAIT1()  asm volatile("cp.async.wait_group 1;\n":::"memory")
__device__ __forceinline__ void splith(float x,f16& h,f16& l){h=__float2half(x);l=__float2half((x-__half2float(h))*LOSCL);}
__device__ __forceinline__ uint32_t packh(f16 a,f16 b){return ((uint32_t)__half_as_ushort(b)<<16)|(uint32_t)__half_as_ushort(a);}

// ---- fp16 hi/lo GEMM, 3 combos, cp.async 2-stage pipelined (R14 proven) ----
#define TGST 15360
#define TG_SMEM (2*TGST*2)
template <int RELU,int HASBIAS,int SCALEQ,int OUTF32,int OUTSPLIT,int PREAUX,int OUTV16,int OUTQKV>
__global__ __launch_bounds__(256) void tgemm(const f16* __restrict__ Ah,const f16* __restrict__ Al,
    const f16* __restrict__ Bh,const f16* __restrict__ Bl,const float* __restrict__ bias,
    float* __restrict__ Cf,f16* __restrict__ Chi,f16* __restrict__ Clo,f16* __restrict__ V16,
    float* __restrict__ Caux,int M,int K){
    extern __shared__ __align__(16) f16 sm[];
    const int tid=threadIdx.x,wid=tid>>5,lane=tid&31;
    const int r=lane>>2,cq=(lane&3)*2,wm=wid>>1,wn=wid&1;
    const int m0=blockIdx.y*128,n0=blockIdx.x*64;
    const int a_ro=(lane&7)+((lane>>3)&1)*8,a_ch=((lane>>4)&1)*8;
    const int b_no=(lane&7)+((lane>>4)&1)*8,b_kh=((lane>>3)&1)*8;
    const int ar=tid>>2,aq=(tid&3)*8;
    const int br=tid>>2,bq=(tid&3)*8;
    float acc[2][4][4]={},acL[2][4][4]={};
    const int nch=K>>5;
    {
        f16* st=sm;
        cpa16(smaddr(st+ar*40+aq),Ah+(size_t)(m0+ar)*K+aq);
        cpa16(smaddr(st+(64+ar)*40+aq),Ah+(size_t)(m0+64+ar)*K+aq);
        cpa16(smaddr(st+5120+ar*40+aq),Al+(size_t)(m0+ar)*K+aq);
        cpa16(smaddr(st+5120+(64+ar)*40+aq),Al+(size_t)(m0+64+ar)*K+aq);
        cpa16(smaddr(st+10240+br*40+bq),Bh+(size_t)(n0+br)*K+bq);
        cpa16(smaddr(st+12800+br*40+bq),Bl+(size_t)(n0+br)*K+bq);
    }
    CP_COMMIT();
    for(int ic=0;ic<nch;ic++){
        __syncthreads();
        if(ic+1<nch){
            f16* st=sm+((ic+1)&1)*TGST;
            int kc=(ic+1)*32;
            cpa16(smaddr(st+ar*40+aq),Ah+(size_t)(m0+ar)*K+kc+aq);
            cpa16(smaddr(st+(64+ar)*40+aq),Ah+(size_t)(m0+64+ar)*K+kc+aq);
            cpa16(smaddr(st+5120+ar*40+aq),Al+(size_t)(m0+ar)*K+kc+aq);
            cpa16(smaddr(st+5120+(64+ar)*40+aq),Al+(size_t)(m0+64+ar)*K+kc+aq);
            cpa16(smaddr(st+10240+br*40+bq),Bh+(size_t)(n0+br)*K+kc+bq);
            cpa16(smaddr(st+12800+br*40+bq),Bl+(size_t)(n0+br)*K+kc+bq);
        }
        CP_COMMIT();
        CP_WAIT1();
        __syncthreads();
        f16* st=sm+(ic&1)*TGST;
        uint32_t aHb[2],aLb[2],bHb,bLb;
        aHb[0]=smaddr(st+(wm*32+a_ro)*40+a_ch);aHb[1]=smaddr(st+(wm*32+16+a_ro)*40+a_ch);
        aLb[0]=smaddr(st+5120+(wm*32+a_ro)*40+a_ch);aLb[1]=smaddr(st+5120+(wm*32+16+a_ro)*40+a_ch);
        bHb=smaddr(st+10240+(wn*32+b_no)*40+b_kh);bLb=smaddr(st+12800+(wn*32+b_no)*40+b_kh);
#pragma unroll
        for(int ks=0;ks<2;ks++){
            uint32_t aH[2][4],aL[2][4];
#pragma unroll
            for(int mf=0;mf<2;mf++){ldsm4(aH[mf],aHb[mf]+ks*32);ldsm4(aL[mf],aLb[mf]+ks*32);}
#pragma unroll
            for(int np=0;np<2;np++){
                uint32_t bH[4],bL[4];
                ldsm4(bH,bHb+np*1280+ks*32);ldsm4(bL,bLb+np*1280+ks*32);
#pragma unroll
                for(int mf=0;mf<2;mf++){
                    mma_f16(acc[mf][np*2],aH[mf][0],aH[mf][1],aH[mf][2],aH[mf][3],bH[0],bH[1]);
                    mma_f16(acL[mf][np*2],aL[mf][0],aL[mf][1],aL[mf][2],aL[mf][3],bH[0],bH[1]);
                    mma_f16(acL[mf][np*2],aH[mf][0],aH[mf][1],aH[mf][2],aH[mf][3],bL[0],bL[1]);
                    mma_f16(acc[mf][np*2+1],aH[mf][0],aH[mf][1],aH[mf][2],aH[mf][3],bH[2],bH[3]);
                    mma_f16(acL[mf][np*2+1],aL[mf][0],aL[mf][1],aL[mf][2],aL[mf][3],bH[2],bH[3]);
                    mma_f16(acL[mf][np*2+1],aH[mf][0],aH[mf][1],aH[mf][2],aH[mf][3],bL[2],bL[3]);
                }
            }
        }
    }
#pragma unroll
    for(int mf=0;mf<2;mf++)
#pragma unroll
    for(int nf=0;nf<4;nf++){
        int mrow=m0+wm*32+mf*16+r,col=n0+wn*32+nf*8+cq;
        float c0=acc[mf][nf][0]+acL[mf][nf][0]*INVLO,c1=acc[mf][nf][1]+acL[mf][nf][1]*INVLO;
        float c2=acc[mf][nf][2]+acL[mf][nf][2]*INVLO,c3=acc[mf][nf][3]+acL[mf][nf][3]*INVLO;
        if(HASBIAS){float b0=bias[col],b1=bias[col+1];c0+=b0;c1+=b1;c2+=b0;c3+=b1;}
        if(SCALEQ){c0*=0.0625f;c1*=0.0625f;c2*=0.0625f;c3*=0.0625f;}
        if(PREAUX){Caux[(size_t)mrow*HD+col]=c0;Caux[(size_t)mrow*HD+col+1]=c1;
            Caux[(size_t)(mrow+8)*HD+col]=c2;Caux[(size_t)(mrow+8)*HD+col+1]=c3;}
        if(RELU){c0=fmaxf(c0,0.f);c1=fmaxf(c1,0.f);c2=fmaxf(c2,0.f);c3=fmaxf(c3,0.f);}
        if(OUTF32){Cf[(size_t)mrow*HD+col]=c0;Cf[(size_t)mrow*HD+col+1]=c1;
            Cf[(size_t)(mrow+8)*HD+col]=c2;Cf[(size_t)(mrow+8)*HD+col+1]=c3;}
        if(OUTSPLIT){f16 h0,l0,h1,l1,h2,l2,h3,l3;
            splith(c0,h0,l0);splith(c1,h1,l1);splith(c2,h2,l2);splith(c3,h3,l3);
            *(uint32_t*)(Chi+(size_t)mrow*HD+col)=packh(h0,h1);
            *(uint32_t*)(Clo+(size_t)mrow*HD+col)=packh(l0,l1);
            *(uint32_t*)(Chi+(size_t)(mrow+8)*HD+col)=packh(h2,h3);
            *(uint32_t*)(Clo+(size_t)(mrow+8)*HD+col)=packh(l2,l3);}
        if(OUTV16){
            *(uint32_t*)(V16+(size_t)mrow*HD+col)=packh(__float2half(c0),__float2half(c1));
            *(uint32_t*)(V16+(size_t)(mrow+8)*HD+col)=packh(__float2half(c2),__float2half(c3));}
        if(OUTQKV){
            int seg=col>>8,cl=col&255;
            f16* dst=(seg==0)?Chi:((seg==1)?Clo:V16);
            float sc=(seg==0)?0.0625f:1.f;
            *(uint32_t*)(dst+(size_t)mrow*HD+cl)=packh(__float2half(c0*sc),__float2half(c1*sc));
            *(uint32_t*)(dst+(size_t)(mrow+8)*HD+cl)=packh(__float2half(c2*sc),__float2half(c3*sc));}
    }
}

#define SZ_WI (HD*KP_WI)
#define SZ_H  (HD*HD)
#define SZ_WO (HD*KP_WO)
__global__ void wsplit_all_k(const float* __restrict__ Wi,const float* __restrict__ Wh,
    const float* __restrict__ Wq,const float* __restrict__ Wk,const float* __restrict__ Wv,
    const float* __restrict__ Wa,const float* __restrict__ Wo){
    int idx=blockIdx.x*blockDim.x+threadIdx.x;
    if(idx>=SZ_WI+SZ_H){
        if(idx<SZ_WI+4*SZ_H){
            int local=idx-SZ_WI-SZ_H,n=local>>8,k=local&255;
            const float* W=(n<256)?Wq:((n<512)?Wk:Wv);
            float x=W[(size_t)k*HD+(n&255)];
            f16 h,l;splith(x,h,l);
            g_Wqkvthi[local]=h;g_Wqkvtlo[local]=l;return;
        }
        if(idx<SZ_WI+5*SZ_H){
            int local=idx-SZ_WI-4*SZ_H,k=local&255,n=local>>8;
            float x=Wa[(size_t)k*HD+n];
            f16 h,l;splith(x,h,l);g_Wathi[local]=h;g_Watlo[local]=l;return;
        }
        if(idx<SZ_WI+5*SZ_H+SZ_WO){
            int local=idx-SZ_WI-5*SZ_H,k=local%KP_WO,n=local/KP_WO;
            float x=(k<FDIM+HD)?Wo[(size_t)k*HD+n]:0.f;
            f16 h,l;splith(x,h,l);g_Wothi[local]=h;g_Wotlo[local]=l;return;
        }
        return;
    }
    if(idx<SZ_WI){
        int k=idx%KP_WI,n=idx/KP_WI;
        float x=(k<BFDIM)?Wi[(size_t)k*HD+n]:0.f;
        f16 h,l;splith(x,h,l);g_Withi[idx]=h;g_Witlo[idx]=l;return;
    }
    {
        int local=idx-SZ_WI,k=local&255,n=local>>8;
        float x=Wh[(size_t)k*HD+n];
        f16 h,l;splith(x,h,l);g_Whthi[local]=h;g_Whtlo[local]=l;
    }
}
__global__ void asplit_k(const float* __restrict__ A,f16* __restrict__ hi,f16* __restrict__ lo,int K,int KPp){
    int idx=blockIdx.x*blockDim.x+threadIdx.x;
    int k=idx%KPp,m=idx/KPp;
    float x=(k<K)?A[(size_t)m*K+k]:0.f;
    f16 h,l;splith(x,h,l);hi[idx]=h;lo[idx]=l;
}
__global__ void w3copy_k(const float* __restrict__ Wq,const float* __restrict__ Wk,const float* __restrict__ Wv){
    int idx=blockIdx.x*blockDim.x+threadIdx.x;
    if(idx>=FDIM*N3)return;
    int k=idx/N3,n=idx%N3;
    g_W3[idx]=(n<FDIM)?Wq[k*FDIM+n]:(n<2*FDIM)?Wk[k*FDIM+n-FDIM]:Wv[k*FDIM+n-2*FDIM];
}

// ---- fp32 GEMM (atom-side) ----
template <int RELU,int HASBIAS>
__global__ __launch_bounds__(256) void gemm_k(const float* __restrict__ A,const float* __restrict__ B,
    const float* __restrict__ bias,float* __restrict__ C,int Mm,int Nn,int Kk){
    __shared__ float As[16*68],Bs[16*68];
    const int tid=threadIdx.x,tm=tid>>4,tn=tid&15;
    const int m0=blockIdx.y*64,n0=blockIdx.x*64;
    float acc[4][4]={};
    for(int k0=0;k0<Kk;k0+=16){
#pragma unroll
        for(int i=0;i<4;i++){int idx=tid+i*256,row=idx>>4,col=idx&15;float v=0.f;
            if(m0+row<Mm&&k0+col<Kk)v=A[(size_t)(m0+row)*Kk+k0+col];As[col*68+row]=v;}
#pragma unroll
        for(int i=0;i<4;i++){int idx=tid+i*256,row=idx>>6,col=idx&63;float v=0.f;
            if(k0+row<Kk&&n0+col<Nn)v=B[(size_t)(k0+row)*Nn+n0+col];Bs[row*68+col]=v;}
        __syncthreads();
#pragma unroll
        for(int kk=0;kk<16;kk++){
            float4 a4=*(const float4*)&As[kk*68+tm*4];
            float4 b4=*(const float4*)&Bs[kk*68+tn*4];
            float av[4]={a4.x,a4.y,a4.z,a4.w},bv[4]={b4.x,b4.y,b4.z,b4.w};
#pragma unroll
            for(int i=0;i<4;i++)
#pragma unroll
                for(int j=0;j<4;j++)acc[i][j]+=av[i]*bv[j];
        }
        __syncthreads();
    }
#pragma unroll
    for(int i=0;i<4;i++){int m=m0+tm*4+i;if(m>=Mm)continue;
#pragma unroll
        for(int j=0;j<4;j++){int n=n0+tn*4+j;if(n>=Nn)continue;
            float v=acc[i][j];if(HASBIAS)v+=bias[n];if(RELU)v=fmaxf(v,0.f);
            C[(size_t)m*Nn+n]=v;}}
}

// ---- flash: fp16 S/O, online max, 3-stage cp.async, softmax pipelined over tiles ----
#define SQH 0
#define SKB 67584
#define KTB 16896
#define SVB (SKB+3*KTB)
#define FL_SMEM (SVB+3*KTB)
__device__ __forceinline__ void fl_pref(char* smem,int stg,int kb,int tid){
    f16* kd=(f16*)(smem+SKB+stg*KTB);f16* vd=(f16*)(smem+SVB+stg*KTB);
#pragma unroll
    for(int i=0;i<4;i++){
        int idx=tid+i*256,row=idx>>5,c8=(idx&31)*8;
        cpa16(smaddr(kd+row*264+c8),g_K16+(size_t)(kb+row)*HD+c8);
        cpa16(smaddr(vd+row*264+c8),g_V16+(size_t)(kb+row)*HD+c8);
    }
}
__device__ __forceinline__ void fl_qk(float sv[4][4],uint32_t qh_a,uint32_t kh_b){
#pragma unroll
    for(int t=0;t<4;t++){sv[t][0]=0.f;sv[t][1]=0.f;sv[t][2]=0.f;sv[t][3]=0.f;}
#pragma unroll
    for(int ks=0;ks<16;ks++){
        uint32_t aH[4];
        ldsm4(aH,qh_a+ks*32);
#pragma unroll
        for(int tp=0;tp<2;tp++){
            uint32_t bH[4];
            ldsm4(bH,kh_b+tp*8448+ks*32);
            mma_f16(sv[tp*2],aH[0],aH[1],aH[2],aH[3],bH[0],bH[1]);
            mma_f16(sv[tp*2+1],aH[0],aH[1],aH[2],aH[3],bH[2],bH[3]);
        }
    }
}
__global__ __launch_bounds__(256,1) void flash_mma(){
    extern __shared__ __align__(16) char smem[];
    f16* sQH=(f16*)(smem+SQH);
    const int tid=threadIdx.x,wid=tid>>5,lane=tid&31;
    const int r=lane>>2,cq=(lane&3)*2;
    const int row0=blockIdx.x*128,half=blockIdx.y,kb0=half*(NB/2);
    const int a_ro=(lane&7)+((lane>>3)&1)*8,a_ch=((lane>>4)&1)*8;
    const int b_no=(lane&7)+((lane>>4)&1)*8,b_kh=((lane>>3)&1)*8;
    const int v_ro=(lane&7)+((lane>>3)&1)*8,v_co=((lane>>4)&1)*8;

    float m0=-1e30f,m1=-1e30f;
#pragma unroll
    for(int i=0;i<16;i++){
        int idx=tid+i*256,row=idx>>5,c8=(idx&31)*8;
        *(uint4*)(sQH+row*264+c8)=*(const uint4*)(g_Q16+(size_t)(row0+row)*HD+c8);
    }
    const uint32_t qh_a=smaddr(sQH+(wid*16+a_ro)*264+a_ch);
    uint32_t kb_s[3],vb_s[3];
#pragma unroll
    for(int s=0;s<3;s++){
        kb_s[s]=smaddr((f16*)(smem+SKB+s*KTB)+b_no*264+b_kh);
        vb_s[s]=smaddr((f16*)(smem+SVB+s*KTB)+v_ro*264+v_co);
    }
    float Oc[32][4];
#pragma unroll
    for(int t=0;t<32;t++){Oc[t][0]=0.f;Oc[t][1]=0.f;Oc[t][2]=0.f;Oc[t][3]=0.f;}
    float l0=0.f,l1=0.f;

    fl_pref(smem,0,kb0,tid);CP_COMMIT();
    fl_pref(smem,1,kb0+32,tid);CP_COMMIT();
    CP_WAIT1();
    __syncthreads();
    float svA[4][4],svB[4][4];
    fl_qk(svA,qh_a,kb_s[0]);

    for(int kt=0;kt<128;kt++){
        __syncthreads();
        if(kt+2<128)fl_pref(smem,(kt+2)%3,kb0+(kt+2)*32,tid);
        CP_COMMIT();
        CP_WAIT1();                // tiles <= kt+1 resident
        __syncthreads();
        // S_{kt+1} MMAs (independent) — overlap with softmax below
        if(kt+1<128)fl_qk(svB,qh_a,kb_s[(kt+1)%3]);
        // softmax of svA
        float tm0=-1e30f,tm1=-1e30f;
#pragma unroll
        for(int t=0;t<4;t++){
            tm0=fmaxf(tm0,fmaxf(svA[t][0],svA[t][1]));
            tm1=fmaxf(tm1,fmaxf(svA[t][2],svA[t][3]));
        }
        tm0=fmaxf(tm0,__shfl_xor_sync(0xffffffffu,tm0,1));
        tm0=fmaxf(tm0,__shfl_xor_sync(0xffffffffu,tm0,2));
        tm1=fmaxf(tm1,__shfl_xor_sync(0xffffffffu,tm1,1));
        tm1=fmaxf(tm1,__shfl_xor_sync(0xffffffffu,tm1,2));
        float mn0=fmaxf(m0,tm0),mn1=fmaxf(m1,tm1);
        float f0=__expf(m0-mn0),f1=__expf(m1-mn1);
        m0=mn0;m1=mn1;
        if(f0!=1.0f||f1!=1.0f){
            l0*=f0;l1*=f1;
#pragma unroll
            for(int t=0;t<32;t++){Oc[t][0]*=f0;Oc[t][1]*=f0;Oc[t][2]*=f1;Oc[t][3]*=f1;}
        }
        uint32_t pH[2][4];
        float rs0=0.f,rs1=0.f;
#pragma unroll
        for(int t=0;t<4;t++){
            float e0=__expf(svA[t][0]-m0),e1=__expf(svA[t][1]-m0);
            float e2=__expf(svA[t][2]-m1),e3=__expf(svA[t][3]-m1);
            rs0+=e0+e1;rs1+=e2+e3;
            int ksp=t>>1,h2=(t&1)*2;
            pH[ksp][h2]=packh(__float2half(e0*PSCL),__float2half(e1*PSCL));
            pH[ksp][h2+1]=packh(__float2half(e2*PSCL),__float2half(e3*PSCL));
        }
        rs0+=__shfl_xor_sync(0xffffffffu,rs0,1);rs0+=__shfl_xor_sync(0xffffffffu,rs0,2);
        rs1+=__shfl_xor_sync(0xffffffffu,rs1,1);rs1+=__shfl_xor_sync(0xffffffffu,rs1,2);
        l0+=rs0;l1+=rs1;
        // O += P V from stage kt%3
        const uint32_t vh_b=vb_s[kt%3];
#pragma unroll
        for(int ks2=0;ks2<2;ks2++)
#pragma unroll
        for(int tp=0;tp<16;tp++){
            uint32_t bH[4];
            ldsm4t(bH,vh_b+ks2*8448+tp*32);
            mma_f16(Oc[tp*2],pH[ks2][0],pH[ks2][1],pH[ks2][2],pH[ks2][3],bH[0],bH[1]);
            mma_f16(Oc[tp*2+1],pH[ks2][0],pH[ks2][1],pH[ks2][2],pH[ks2][3],bH[2],bH[3]);
        }
        if(kt+1<128){
#pragma unroll
            for(int t=0;t<4;t++){
                svA[t][0]=svB[t][0];svA[t][1]=svB[t][1];
                svA[t][2]=svB[t][2];svA[t][3]=svB[t][3];
            }
        }
    }
    {
        int rg=row0+wid*16+r;
        float* O=g_Opart+(size_t)half*NB*HD;
#pragma unroll
        for(int t=0;t<32;t++){
            int col=t*8+cq;
            O[(size_t)rg*HD+col]=Oc[t][0];O[(size_t)rg*HD+col+1]=Oc[t][1];
            O[(size_t)(rg+8)*HD+col]=Oc[t][2];O[(size_t)(rg+8)*HD+col+1]=Oc[t][3];
        }
        if((lane&3)==0){
            g_lpart[half*NB+rg]=l0;g_lpart[half*NB+rg+8]=l1;
            g_mpart[half*NB+rg]=m0;g_mpart[half*NB+rg+8]=m1;
        }
    }
}
__global__ void flash_merge_k(){
    int row=blockIdx.x,c=threadIdx.x;
    float ma=g_mpart[row],mb=g_mpart[NB+row];
    float m=fmaxf(ma,mb);
    float wa=__expf(ma-m),wb=__expf(mb-m);
    float denom=(g_lpart[row]*wa+g_lpart[NB+row]*wb)*PSCL;
    size_t o=(size_t)row*HD+c;
    float v=(g_Opart[o]*wa+g_Opart[(size_t)NB*HD+o]*wb)/denom;
    f16 h,l;splith(v,h,l);
    g_avhi[o]=h;g_avlo[o]=l;
}

// ---- atom self-attn + LN (stride 137) ----
#define ATP 137
#define AT_SMEM_FLOATS (4*64*ATP+64*64+512+128)
__global__ __launch_bounds__(256,1) void atom_attn_ln_k(const float* __restrict__ xg,
    const float* __restrict__ gw,const float* __restrict__ bw){
    extern __shared__ float smf[];
    float* sx=smf;float* sq=sx+64*ATP;float* sk=sq+64*ATP;float* sv=sk+64*ATP;
    float* ss=sv+64*ATP;float* sred=ss+4096;float* srow=sred+512;
    const int tid=threadIdx.x,base=blockIdx.x*64;
    for(int idx=tid;idx<64*FDIM;idx+=256){
        int a=idx/FDIM,f=idx-a*FDIM;
        sx[a*ATP+f]=xg[(size_t)(base+a)*FDIM+f];
        size_t go=(size_t)(base+a)*N3+f;
        sq[a*ATP+f]=g_qkv[go];sk[a*ATP+f]=g_qkv[go+FDIM];sv[a*ATP+f]=g_qkv[go+2*FDIM];
    }
    __syncthreads();
    {
        int ty=tid>>4,tx=tid&15;float acc[4][4]={};
        for(int h=0;h<FDIM;h++){
            float qv[4],kv[4];
#pragma unroll
            for(int i=0;i<4;i++){qv[i]=sq[(ty*4+i)*ATP+h];kv[i]=sk[(tx*4+i)*ATP+h];}
#pragma unroll
            for(int i=0;i<4;i++)
#pragma unroll
                for(int j=0;j<4;j++)acc[i][j]+=qv[i]*kv[j];
        }
        float scl=rsqrtf(133.0f);
#pragma unroll
        for(int i=0;i<4;i++)
#pragma unroll
            for(int j=0;j<4;j++)ss[(ty*4+i)*64+tx*4+j]=acc[i][j]*scl;
    }
    __syncthreads();
    if(tid<64){
        float mx=-1e30f;
        for(int j=0;j<64;j++)mx=fmaxf(mx,ss[tid*64+j]);
        float s=0.f;
        for(int j=0;j<64;j++){float e=__expf(ss[tid*64+j]-mx);ss[tid*64+j]=e;s+=e;}
        float inv=1.f/s;
        for(int j=0;j<64;j++)ss[tid*64+j]*=inv;
    }
    __syncthreads();
    const int r=tid>>2,qd=tid&3,f0=qd*34;
    float tv[34];
#pragma unroll
    for(int f=0;f<34;f++)tv[f]=0.f;
    for(int b=0;b<64;b++){
        float p=ss[r*64+b];const float* vb=&sv[b*ATP+f0];
#pragma unroll
        for(int f=0;f<34;f++)if(f0+f<FDIM)tv[f]+=p*vb[f];
    }
    float s1=0.f;
#pragma unroll
    for(int f=0;f<34;f++)if(f0+f<FDIM){tv[f]+=sx[r*ATP+f0+f];s1+=tv[f];}
    sred[tid]=s1;__syncthreads();
    if(qd==0)srow[r]=(sred[tid]+sred[tid+1]+sred[tid+2]+sred[tid+3])*(1.f/133.f);
    __syncthreads();
    float mu=srow[r],s2=0.f;
#pragma unroll
    for(int f=0;f<34;f++)if(f0+f<FDIM){float d=tv[f]-mu;s2+=d*d;}
    sred[tid]=s2;__syncthreads();
    if(qd==0){float var=(sred[tid]+sred[tid+1]+sred[tid+2]+sred[tid+3])*(1.f/133.f);srow[64+r]=rsqrtf(var+1e-5f);}
    __syncthreads();
    float rstd=srow[64+r];
#pragma unroll
    for(int f=0;f<34;f++){int fg=f0+f;
        if(fg<FDIM)g_fe[(size_t)(base+r)*FDIM+fg]=(tv[f]-mu)*rstd*gw[fg]+bw[fg];}
}

__global__ void gather_sum_k(const int* __restrict__ a2b){
    __shared__ int idx[MAXNB];
    int a=blockIdx.x,t=threadIdx.x;
    if(t<MAXNB)idx[t]=a2b[a*MAXNB+t];
    __syncthreads();
    float s=0.f;
#pragma unroll
    for(int j=0;j<MAXNB;j++)s+=g_msg[(size_t)idx[j]*HD+t];
    g_amsg[(size_t)a*HD+t]=s;
}
__global__ void dmpnn_fused_k(const int* __restrict__ a2b,const int* __restrict__ b2a,
    const int* __restrict__ b2revb){
    __shared__ int idx[MAXNB+1];
    int b=blockIdx.x,t=threadIdx.x;
    if(t==0){
        int ia=__ldg(&b2a[b]);
#pragma unroll
        for(int j=0;j<MAXNB;j++)idx[j]=__ldg(&a2b[ia*MAXNB+j]);
        idx[MAXNB]=__ldg(&b2revb[b]);
    }
    __syncthreads();
    float s=0.f;
#pragma unroll
    for(int j=0;j<MAXNB;j++)s+=g_msg[(size_t)idx[j]*HD+t];
    float v=s-g_msg[(size_t)idx[MAXNB]*HD+t];
    f16 h,l;splith(v,h,l);
    size_t o=(size_t)b*HD+t;
    g_tmphi[o]=h;g_tmplo[o]=l;
}
__global__ void combine_k(const float* __restrict__ wal,const float* __restrict__ walb){
    __shared__ float red[256];
    __shared__ float salpha;
    int b=blockIdx.x,t=threadIdx.x;
    size_t o=(size_t)b*HD+t;
    float d=g_dmpnn[o],am=g_attm[o];
    red[t]=d*wal[t]+am*wal[256+t];
    __syncthreads();
    for(int s=128;s>0;s>>=1){if(t<s)red[t]+=red[t+s];__syncthreads();}
    if(t==0)salpha=1.f/(1.f+__expf(-(red[0]+walb[0])));
    __syncthreads();
    float al=salpha;
    float v=fmaxf(g_inputs[o]+al*d+(1.f-al)*am,0.f);
    g_msg[o]=v;
    f16 h,l;splith(v,h,l);
    g_msghi[o]=h;g_msglo[o]=l;
}
__global__ void concat_split_k(){
    int i=blockIdx.x*blockDim.x+threadIdx.x;
    if(i>=NA*KP_WO)return;
    int row=i/KP_WO,c=i-row*KP_WO;
    float x=(c<FDIM)?g_fe[(size_t)row*FDIM+c]:(c<FDIM+HD?g_amsg[(size_t)row*HD+(c-FDIM)]:0.f);
    f16 h,l;splith(x,h,l);
    g_cathi[i]=h;g_catlo[i]=l;
}

#define MP_SMEM_FLOATS (2*64*260+4096)
__global__ __launch_bounds__(256,1) void mol_pool_k(const float* __restrict__ Wb,
    const float* __restrict__ bb,float* __restrict__ outg){
    extern __shared__ float smf[];
    float* shm=smf;float* sw=shm+64*260;float* ssc=sw+64*260;
    const int tid=threadIdx.x,base=blockIdx.x*64;
    for(int idx=tid;idx<64*HD;idx+=256){
        int a=idx>>8,c=idx&255;
        shm[a*260+c]=g_atomh[(size_t)(base+a)*HD+c];
        sw[a*260+c]=g_hmwa[(size_t)(base+a)*HD+c];
    }
    __syncthreads();
    {
        int ty=tid>>4,tx=tid&15;float acc[4][4]={};
        for(int h=0;h<HD;h++){
            float qv[4],kv[4];
#pragma unroll
            for(int i=0;i<4;i++){qv[i]=sw[(ty*4+i)*260+h];kv[i]=shm[(tx*4+i)*260+h];}
#pragma unroll
            for(int i=0;i<4;i++)
#pragma unroll
                for(int j=0;j<4;j++)acc[i][j]+=qv[i]*kv[j];
        }
#pragma unroll
        for(int i=0;i<4;i++)
#pragma unroll
            for(int j=0;j<4;j++)ssc[(ty*4+i)*64+tx*4+j]=acc[i][j];
    }
    __syncthreads();
    if(tid<64){
        float mx=-1e30f;
        for(int j=0;j<64;j++)mx=fmaxf(mx,ssc[tid*64+j]);
        float s=0.f;
        for(int j=0;j<64;j++){float e=__expf(ssc[tid*64+j]-mx);ssc[tid*64+j]=e;s+=e;}
        float inv=1.f/s;
        for(int j=0;j<64;j++)ssc[tid*64+j]*=inv;
    }
    __syncthreads();
    const int c=tid;
    float acc[64];
#pragma unroll
    for(int a=0;a<64;a++)acc[a]=0.f;
    for(int b=0;b<64;b++){
        float hv=shm[b*260+c];
#pragma unroll 16
        for(int a=0;a<64;a++)acc[a]+=ssc[a*64+b]*hv;
    }
    __syncthreads();
    for(int a=0;a<64;a++)sw[a*260+c]=acc[a];
    __syncthreads();
#pragma unroll
    for(int a=0;a<64;a++)acc[a]=0.f;
    for(int k=0;k<HD;k++){
        float wv=Wb[(size_t)k*HD+c];
#pragma unroll 16
        for(int a=0;a<64;a++)acc[a]+=sw[a*260+k]*wv;
    }
    float bv=bb[c],s=0.f;
    for(int a=0;a<64;a++){float t=fmaxf(acc[a]+bv,0.f);s+=shm[a*260+c]+t;}
    outg[(size_t)blockIdx.x*HD+c]=s*(1.f/64.f);
}

static float* symf(const void* s){void* p=nullptr;cudaGetSymbolAddress(&p,s);return (float*)p;}
static f16* symh(const void* s){void* p=nullptr;cudaGetSymbolAddress(&p,s);return (f16*)p;}

extern "C" void kernel_launch(void* const* d_in,const int* in_sizes,int n_in,void* d_out,int out_size){
    const float* f_atoms=(const float*)d_in[0];
    const float* f_bonds=(const float*)d_in[1];
    const float* Wq_atom=(const float*)d_in[2];
    const float* Wk_atom=(const float*)d_in[3];
    const float* Wv_atom=(const float*)d_in[4];
    const float* ln_g=(const float*)d_in[5];
    const float* ln_b=(const float*)d_in[6];
    const float* Wi=(const float*)d_in[7];
    const float* Wh=(const float*)d_in[8];
    const float* Wq=(const float*)d_in[9];
    const float* Wk=(const float*)d_in[10];
    const float* Wv=(const float*)d_in[11];
    const float* Wa=(const float*)d_in[12];
    const float* Walw=(const float*)d_in[13];
    const float* Walb=(const float*)d_in[14];
    const float* Wow=(const float*)d_in[15];
    const float* Wob=(const float*)d_in[16];
    const float* Wbw=(const float*)d_in[17];
    const float* Wbb=(const float*)d_in[18];
    const int* a2b=(const int*)d_in[19];
    const int* b2a=(const int*)d_in[20];
    const int* b2revb=(const int*)d_in[21];
    float* out=(float*)d_out;

    float* p_W3=symf(g_W3);float* p_qkv=symf(g_qkv);
    float* p_inputs=symf(g_inputs);float* p_msg=symf(g_msg);
    float* p_dmpnn=symf(g_dmpnn);float* p_attm=symf(g_attm);
    float* p_atomh=symf(g_atomh);float* p_hmwa=symf(g_hmwa);
    f16* p_Q16=symh(g_Q16);f16* p_K16=symh(g_K16);f16* p_V16=symh(g_V16);
    f16* p_msghi=symh(g_msghi);f16* p_msglo=symh(g_msglo);
    f16* p_tmphi=symh(g_tmphi);f16* p_tmplo=symh(g_tmplo);
    f16* p_avhi=symh(g_avhi);f16* p_avlo=symh(g_avlo);
    f16* p_fbhi=symh(g_fbhi);f16* p_fblo=symh(g_fblo);
    f16* p_cathi=symh(g_cathi);f16* p_catlo=symh(g_catlo);
    f16* p_ahhi=symh(g_ahhi);f16* p_ahlo=symh(g_ahlo);
    f16* p_Withi=symh(g_Withi);f16* p_Witlo=symh(g_Witlo);
    f16* p_Whthi=symh(g_Whthi);f16* p_Whtlo=symh(g_Whtlo);
    f16* p_Wqkvthi=symh(g_Wqkvthi);f16* p_Wqkvtlo=symh(g_Wqkvtlo);
    f16* p_Wathi=symh(g_Wathi);f16* p_Watlo=symh(g_Watlo);
    f16* p_Wothi=symh(g_Wothi);f16* p_Wotlo=symh(g_Wotlo);

    const int AT_SMEM=AT_SMEM_FLOATS*4,MP_SMEM=MP_SMEM_FLOATS*4;
    cudaFuncSetAttribute(flash_mma,cudaFuncAttributeMaxDynamicSharedMemorySize,FL_SMEM);
    cudaFuncSetAttribute(atom_attn_ln_k,cudaFuncAttributeMaxDynamicSharedMemorySize,AT_SMEM);
    cudaFuncSetAttribute(mol_pool_k,cudaFuncAttributeMaxDynamicSharedMemorySize,MP_SMEM);
    cudaFuncSetAttribute(tgemm<1,0,0,1,1,1,0,0>,cudaFuncAttributeMaxDynamicSharedMemorySize,TG_SMEM);
    cudaFuncSetAttribute(tgemm<0,0,0,1,0,0,0,0>,cudaFuncAttributeMaxDynamicSharedMemorySize,TG_SMEM);
    cudaFuncSetAttribute(tgemm<0,0,0,0,0,0,0,1>,cudaFuncAttributeMaxDynamicSharedMemorySize,TG_SMEM);
    cudaFuncSetAttribute(tgemm<1,1,0,1,1,0,0,0>,cudaFuncAttributeMaxDynamicSharedMemorySize,TG_SMEM);

    const int WALL=SZ_WI+5*SZ_H+SZ_WO;
    wsplit_all_k<<<(WALL+255)/256,256>>>(Wi,Wh,Wq,Wk,Wv,Wa,Wow);
    asplit_k<<<(NB*KP_WI)/256,256>>>(f_bonds,p_fbhi,p_fblo,BFDIM,KP_WI);
    w3copy_k<<<(FDIM*N3+255)/256,256>>>(Wq_atom,Wk_atom,Wv_atom);

    dim3 gqa((N3+63)/64,(NA+63)/64);
    gemm_k<0,0><<<gqa,256>>>(f_atoms,p_W3,nullptr,p_qkv,NA,N3,FDIM);
    atom_attn_ln_k<<<NMOL,256,AT_SMEM>>>(f_atoms,ln_g,ln_b);

    dim3 tgb(4,NB/128),tga(4,NA/128),tgqkv(12,NB/128);
    tgemm<1,0,0,1,1,1,0,0><<<tgb,256,TG_SMEM>>>(p_fbhi,p_fblo,p_Withi,p_Witlo,nullptr,
        p_msg,p_msghi,p_msglo,nullptr,p_inputs,NB,KP_WI);

    for(int it=0;it<3;it++){
        dmpnn_fused_k<<<NB,256>>>(a2b,b2a,b2revb);
        tgemm<0,0,0,1,0,0,0,0><<<tgb,256,TG_SMEM>>>(p_tmphi,p_tmplo,p_Whthi,p_Whtlo,nullptr,
            p_dmpnn,nullptr,nullptr,nullptr,nullptr,NB,HD);
        tgemm<0,0,0,0,0,0,0,1><<<tgqkv,256,TG_SMEM>>>(p_msghi,p_msglo,p_Wqkvthi,p_Wqkvtlo,nullptr,
            nullptr,p_Q16,p_K16,p_V16,nullptr,NB,HD);
        flash_mma<<<dim3(NB/128,2),256,FL_SMEM>>>();
        flash_merge_k<<<NB,256>>>();
        tgemm<0,0,0,1,0,0,0,0><<<tgb,256,TG_SMEM>>>(p_avhi,p_avlo,p_Wathi,p_Watlo,nullptr,
            p_attm,nullptr,nullptr,nullptr,nullptr,NB,HD);
        combine_k<<<NB,256>>>(Walw,Walb);
    }

    gather_sum_k<<<NA,256>>>(a2b);
    concat_split_k<<<(NA*KP_WO+255)/256,256>>>();
    tgemm<1,1,0,1,1,0,0,0><<<tga,256,TG_SMEM>>>(p_cathi,p_catlo,p_Wothi,p_Wotlo,Wob,
        p_atomh,p_ahhi,p_ahlo,nullptr,nullptr,NA,KP_WO);
    tgemm<0,0,0,1,0,0,0,0><<<tga,256,TG_SMEM>>>(p_ahhi,p_ahlo,p_Wathi,p_Watlo,nullptr,
        p_hmwa,nullptr,nullptr,nullptr,nullptr,NA,HD);
    mol_pool_k<<<NMOL,256,MP_SMEM>>>(Wbw,Wbb,out);
}

// round 16
// speedup vs baseline: 1.0509x; 1.0509x over previous
#include <cuda_runtime.h>
#include <cuda_fp16.h>
#include <math.h>
#include <stdint.h>
#define NA 4096
#define NB 8192
#define FDIM 133
#define BFDIM 147
#define HD 256
#define NMOL 64
#define MAXNB 6
#define KP_WI 160
#define KP_WO 416
#define N3 399
#define LOSCL 2048.0f
#define INVLO (1.0f/2048.0f)
#define PSCL 1024.0f
typedef __half f16;

__device__ __align__(16) float g_W3[FDIM*N3];
__device__ __align__(16) float g_qkv[NA*N3];
__device__ __align__(16) float g_fe[NA*FDIM];
__device__ __align__(16) float g_inputs[NB*HD];
__device__ __align__(16) float g_msg[NB*HD];
__device__ __align__(16) float g_amsg[NA*HD];
__device__ __align__(16) float g_dmpnn[NB*HD];
__device__ __align__(16) float g_attm[NB*HD];
__device__ __align__(16) float g_atomh[NA*HD];
__device__ __align__(16) float g_hmwa[NA*HD];
__device__ __align__(16) float g_Opart[2*NB*HD];
__device__ __align__(16) float g_lpart[2*NB];
__device__ __align__(16) float g_mpart[2*NB];
__device__ __align__(16) f16 g_Q16[NB*HD];
__device__ __align__(16) f16 g_K16[NB*HD];
__device__ __align__(16) f16 g_V16[NB*HD];
__device__ __align__(16) f16 g_msghi[NB*HD];
__device__ __align__(16) f16 g_msglo[NB*HD];
__device__ __align__(16) f16 g_tmphi[NB*HD];
__device__ __align__(16) f16 g_tmplo[NB*HD];
__device__ __align__(16) f16 g_avhi[NB*HD];
__device__ __align__(16) f16 g_avlo[NB*HD];
__device__ __align__(16) f16 g_fbhi[NB*KP_WI];
__device__ __align__(16) f16 g_fblo[NB*KP_WI];
__device__ __align__(16) f16 g_cathi[NA*KP_WO];
__device__ __align__(16) f16 g_catlo[NA*KP_WO];
__device__ __align__(16) f16 g_ahhi[NA*HD];
__device__ __align__(16) f16 g_ahlo[NA*HD];
__device__ __align__(16) f16 g_Withi[HD*KP_WI];
__device__ __align__(16) f16 g_Witlo[HD*KP_WI];
__device__ __align__(16) f16 g_Whthi[HD*HD];
__device__ __align__(16) f16 g_Whtlo[HD*HD];
__device__ __align__(16) f16 g_Wqkvthi[3*HD*HD];
__device__ __align__(16) f16 g_Wqkvtlo[3*HD*HD];
__device__ __align__(16) f16 g_Wathi[HD*HD];
__device__ __align__(16) f16 g_Watlo[HD*HD];
__device__ __align__(16) f16 g_Wothi[HD*KP_WO];
__device__ __align__(16) f16 g_Wotlo[HD*KP_WO];

__device__ __forceinline__ void mma_f16(float* c,uint32_t a0,uint32_t a1,uint32_t a2,uint32_t a3,uint32_t b0,uint32_t b1){
    asm("mma.sync.aligned.m16n8k16.row.col.f32.f16.f16.f32 {%0,%1,%2,%3},{%4,%5,%6,%7},{%8,%9},{%0,%1,%2,%3};\n"
        :"+f"(c[0]),"+f"(c[1]),"+f"(c[2]),"+f"(c[3]):"r"(a0),"r"(a1),"r"(a2),"r"(a3),"r"(b0),"r"(b1));
}
__device__ __forceinline__ uint32_t smaddr(const void* p){return (uint32_t)__cvta_generic_to_shared(p);}
__device__ __forceinline__ void ldsm4(uint32_t* r,uint32_t a){
    asm volatile("ldmatrix.sync.aligned.m8n8.x4.shared.b16 {%0,%1,%2,%3},[%4];":"=r"(r[0]),"=r"(r[1]),"=r"(r[2]),"=r"(r[3]):"r"(a));
}
__device__ __forceinline__ void ldsm4t(uint32_t* r,uint32_t a){
    asm volatile("ldmatrix.sync.aligned.m8n8.x4.trans.shared.b16 {%0,%1,%2,%3},[%4];":"=r"(r[0]),"=r"(r[1]),"=r"(r[2]),"=r"(r[3]):"r"(a));
}
__device__ __forceinline__ void cpa16(uint32_t s,const void* g){
    asm volatile("cp.async.ca.shared.global [%0],[%1],16;\n"::"r"(s),"l"(g));
}
#define CP_COMMIT() asm volatile("cp.async.commit_group;\n":::"memory")
#define CP_WAIT1()  asm volatile("cp.async.wait_group 1;\n":::"memory")
__device__ __forceinline__ void splith(float x,f16& h,f16& l){h=__float2half(x);l=__float2half((x-__half2float(h))*LOSCL);}
__device__ __forceinline__ uint32_t packh(f16 a,f16 b){return ((uint32_t)__half_as_ushort(b)<<16)|(uint32_t)__half_as_ushort(a);}

// ---- fp16 hi/lo GEMM, 3 combos, cp.async 2-stage pipelined (R14 proven) ----
#define TGST 15360
#define TG_SMEM (2*TGST*2)
template <int RELU,int HASBIAS,int SCALEQ,int OUTF32,int OUTSPLIT,int PREAUX,int OUTV16,int OUTQKV>
__global__ __launch_bounds__(256) void tgemm(const f16* __restrict__ Ah,const f16* __restrict__ Al,
    const f16* __restrict__ Bh,const f16* __restrict__ Bl,const float* __restrict__ bias,
    float* __restrict__ Cf,f16* __restrict__ Chi,f16* __restrict__ Clo,f16* __restrict__ V16,
    float* __restrict__ Caux,int M,int K){
    extern __shared__ __align__(16) f16 sm[];
    const int tid=threadIdx.x,wid=tid>>5,lane=tid&31;
    const int r=lane>>2,cq=(lane&3)*2,wm=wid>>1,wn=wid&1;
    const int m0=blockIdx.y*128,n0=blockIdx.x*64;
    const int a_ro=(lane&7)+((lane>>3)&1)*8,a_ch=((lane>>4)&1)*8;
    const int b_no=(lane&7)+((lane>>4)&1)*8,b_kh=((lane>>3)&1)*8;
    const int ar=tid>>2,aq=(tid&3)*8;
    const int br=tid>>2,bq=(tid&3)*8;
    float acc[2][4][4]={},acL[2][4][4]={};
    const int nch=K>>5;
    {
        f16* st=sm;
        cpa16(smaddr(st+ar*40+aq),Ah+(size_t)(m0+ar)*K+aq);
        cpa16(smaddr(st+(64+ar)*40+aq),Ah+(size_t)(m0+64+ar)*K+aq);
        cpa16(smaddr(st+5120+ar*40+aq),Al+(size_t)(m0+ar)*K+aq);
        cpa16(smaddr(st+5120+(64+ar)*40+aq),Al+(size_t)(m0+64+ar)*K+aq);
        cpa16(smaddr(st+10240+br*40+bq),Bh+(size_t)(n0+br)*K+bq);
        cpa16(smaddr(st+12800+br*40+bq),Bl+(size_t)(n0+br)*K+bq);
    }
    CP_COMMIT();
    for(int ic=0;ic<nch;ic++){
        __syncthreads();
        if(ic+1<nch){
            f16* st=sm+((ic+1)&1)*TGST;
            int kc=(ic+1)*32;
            cpa16(smaddr(st+ar*40+aq),Ah+(size_t)(m0+ar)*K+kc+aq);
            cpa16(smaddr(st+(64+ar)*40+aq),Ah+(size_t)(m0+64+ar)*K+kc+aq);
            cpa16(smaddr(st+5120+ar*40+aq),Al+(size_t)(m0+ar)*K+kc+aq);
            cpa16(smaddr(st+5120+(64+ar)*40+aq),Al+(size_t)(m0+64+ar)*K+kc+aq);
            cpa16(smaddr(st+10240+br*40+bq),Bh+(size_t)(n0+br)*K+kc+bq);
            cpa16(smaddr(st+12800+br*40+bq),Bl+(size_t)(n0+br)*K+kc+bq);
        }
        CP_COMMIT();
        CP_WAIT1();
        __syncthreads();
        f16* st=sm+(ic&1)*TGST;
        uint32_t aHb[2],aLb[2],bHb,bLb;
        aHb[0]=smaddr(st+(wm*32+a_ro)*40+a_ch);aHb[1]=smaddr(st+(wm*32+16+a_ro)*40+a_ch);
        aLb[0]=smaddr(st+5120+(wm*32+a_ro)*40+a_ch);aLb[1]=smaddr(st+5120+(wm*32+16+a_ro)*40+a_ch);
        bHb=smaddr(st+10240+(wn*32+b_no)*40+b_kh);bLb=smaddr(st+12800+(wn*32+b_no)*40+b_kh);
#pragma unroll
        for(int ks=0;ks<2;ks++){
            uint32_t aH[2][4],aL[2][4];
#pragma unroll
            for(int mf=0;mf<2;mf++){ldsm4(aH[mf],aHb[mf]+ks*32);ldsm4(aL[mf],aLb[mf]+ks*32);}
#pragma unroll
            for(int np=0;np<2;np++){
                uint32_t bH[4],bL[4];
                ldsm4(bH,bHb+np*1280+ks*32);ldsm4(bL,bLb+np*1280+ks*32);
#pragma unroll
                for(int mf=0;mf<2;mf++){
                    mma_f16(acc[mf][np*2],aH[mf][0],aH[mf][1],aH[mf][2],aH[mf][3],bH[0],bH[1]);
                    mma_f16(acL[mf][np*2],aL[mf][0],aL[mf][1],aL[mf][2],aL[mf][3],bH[0],bH[1]);
                    mma_f16(acL[mf][np*2],aH[mf][0],aH[mf][1],aH[mf][2],aH[mf][3],bL[0],bL[1]);
                    mma_f16(acc[mf][np*2+1],aH[mf][0],aH[mf][1],aH[mf][2],aH[mf][3],bH[2],bH[3]);
                    mma_f16(acL[mf][np*2+1],aL[mf][0],aL[mf][1],aL[mf][2],aL[mf][3],bH[2],bH[3]);
                    mma_f16(acL[mf][np*2+1],aH[mf][0],aH[mf][1],aH[mf][2],aH[mf][3],bL[2],bL[3]);
                }
            }
        }
    }
#pragma unroll
    for(int mf=0;mf<2;mf++)
#pragma unroll
    for(int nf=0;nf<4;nf++){
        int mrow=m0+wm*32+mf*16+r,col=n0+wn*32+nf*8+cq;
        float c0=acc[mf][nf][0]+acL[mf][nf][0]*INVLO,c1=acc[mf][nf][1]+acL[mf][nf][1]*INVLO;
        float c2=acc[mf][nf][2]+acL[mf][nf][2]*INVLO,c3=acc[mf][nf][3]+acL[mf][nf][3]*INVLO;
        if(HASBIAS){float b0=bias[col],b1=bias[col+1];c0+=b0;c1+=b1;c2+=b0;c3+=b1;}
        if(SCALEQ){c0*=0.0625f;c1*=0.0625f;c2*=0.0625f;c3*=0.0625f;}
        if(PREAUX){Caux[(size_t)mrow*HD+col]=c0;Caux[(size_t)mrow*HD+col+1]=c1;
            Caux[(size_t)(mrow+8)*HD+col]=c2;Caux[(size_t)(mrow+8)*HD+col+1]=c3;}
        if(RELU){c0=fmaxf(c0,0.f);c1=fmaxf(c1,0.f);c2=fmaxf(c2,0.f);c3=fmaxf(c3,0.f);}
        if(OUTF32){Cf[(size_t)mrow*HD+col]=c0;Cf[(size_t)mrow*HD+col+1]=c1;
            Cf[(size_t)(mrow+8)*HD+col]=c2;Cf[(size_t)(mrow+8)*HD+col+1]=c3;}
        if(OUTSPLIT){f16 h0,l0,h1,l1,h2,l2,h3,l3;
            splith(c0,h0,l0);splith(c1,h1,l1);splith(c2,h2,l2);splith(c3,h3,l3);
            *(uint32_t*)(Chi+(size_t)mrow*HD+col)=packh(h0,h1);
            *(uint32_t*)(Clo+(size_t)mrow*HD+col)=packh(l0,l1);
            *(uint32_t*)(Chi+(size_t)(mrow+8)*HD+col)=packh(h2,h3);
            *(uint32_t*)(Clo+(size_t)(mrow+8)*HD+col)=packh(l2,l3);}
        if(OUTV16){
            *(uint32_t*)(V16+(size_t)mrow*HD+col)=packh(__float2half(c0),__float2half(c1));
            *(uint32_t*)(V16+(size_t)(mrow+8)*HD+col)=packh(__float2half(c2),__float2half(c3));}
        if(OUTQKV){
            int seg=col>>8,cl=col&255;
            f16* dst=(seg==0)?Chi:((seg==1)?Clo:V16);
            float sc=(seg==0)?0.0625f:1.f;
            *(uint32_t*)(dst+(size_t)mrow*HD+cl)=packh(__float2half(c0*sc),__float2half(c1*sc));
            *(uint32_t*)(dst+(size_t)(mrow+8)*HD+cl)=packh(__float2half(c2*sc),__float2half(c3*sc));}
    }
}

#define SZ_WI (HD*KP_WI)
#define SZ_H  (HD*HD)
#define SZ_WO (HD*KP_WO)
__global__ void wsplit_all_k(const float* __restrict__ Wi,const float* __restrict__ Wh,
    const float* __restrict__ Wq,const float* __restrict__ Wk,const float* __restrict__ Wv,
    const float* __restrict__ Wa,const float* __restrict__ Wo){
    int idx=blockIdx.x*blockDim.x+threadIdx.x;
    if(idx>=SZ_WI+SZ_H){
        if(idx<SZ_WI+4*SZ_H){
            int local=idx-SZ_WI-SZ_H,n=local>>8,k=local&255;
            const float* W=(n<256)?Wq:((n<512)?Wk:Wv);
            float x=W[(size_t)k*HD+(n&255)];
            f16 h,l;splith(x,h,l);
            g_Wqkvthi[local]=h;g_Wqkvtlo[local]=l;return;
        }
        if(idx<SZ_WI+5*SZ_H){
            int local=idx-SZ_WI-4*SZ_H,k=local&255,n=local>>8;
            float x=Wa[(size_t)k*HD+n];
            f16 h,l;splith(x,h,l);g_Wathi[local]=h;g_Watlo[local]=l;return;
        }
        if(idx<SZ_WI+5*SZ_H+SZ_WO){
            int local=idx-SZ_WI-5*SZ_H,k=local%KP_WO,n=local/KP_WO;
            float x=(k<FDIM+HD)?Wo[(size_t)k*HD+n]:0.f;
            f16 h,l;splith(x,h,l);g_Wothi[local]=h;g_Wotlo[local]=l;return;
        }
        return;
    }
    if(idx<SZ_WI){
        int k=idx%KP_WI,n=idx/KP_WI;
        float x=(k<BFDIM)?Wi[(size_t)k*HD+n]:0.f;
        f16 h,l;splith(x,h,l);g_Withi[idx]=h;g_Witlo[idx]=l;return;
    }
    {
        int local=idx-SZ_WI,k=local&255,n=local>>8;
        float x=Wh[(size_t)k*HD+n];
        f16 h,l;splith(x,h,l);g_Whthi[local]=h;g_Whtlo[local]=l;
    }
}
__global__ void asplit_k(const float* __restrict__ A,f16* __restrict__ hi,f16* __restrict__ lo,int K,int KPp){
    int idx=blockIdx.x*blockDim.x+threadIdx.x;
    int k=idx%KPp,m=idx/KPp;
    float x=(k<K)?A[(size_t)m*K+k]:0.f;
    f16 h,l;splith(x,h,l);hi[idx]=h;lo[idx]=l;
}
__global__ void w3copy_k(const float* __restrict__ Wq,const float* __restrict__ Wk,const float* __restrict__ Wv){
    int idx=blockIdx.x*blockDim.x+threadIdx.x;
    if(idx>=FDIM*N3)return;
    int k=idx/N3,n=idx%N3;
    g_W3[idx]=(n<FDIM)?Wq[k*FDIM+n]:(n<2*FDIM)?Wk[k*FDIM+n-FDIM]:Wv[k*FDIM+n-2*FDIM];
}

// ---- fp32 GEMM (atom-side) ----
template <int RELU,int HASBIAS>
__global__ __launch_bounds__(256) void gemm_k(const float* __restrict__ A,const float* __restrict__ B,
    const float* __restrict__ bias,float* __restrict__ C,int Mm,int Nn,int Kk){
    __shared__ float As[16*68],Bs[16*68];
    const int tid=threadIdx.x,tm=tid>>4,tn=tid&15;
    const int m0=blockIdx.y*64,n0=blockIdx.x*64;
    float acc[4][4]={};
    for(int k0=0;k0<Kk;k0+=16){
#pragma unroll
        for(int i=0;i<4;i++){int idx=tid+i*256,row=idx>>4,col=idx&15;float v=0.f;
            if(m0+row<Mm&&k0+col<Kk)v=A[(size_t)(m0+row)*Kk+k0+col];As[col*68+row]=v;}
#pragma unroll
        for(int i=0;i<4;i++){int idx=tid+i*256,row=idx>>6,col=idx&63;float v=0.f;
            if(k0+row<Kk&&n0+col<Nn)v=B[(size_t)(k0+row)*Nn+n0+col];Bs[row*68+col]=v;}
        __syncthreads();
#pragma unroll
        for(int kk=0;kk<16;kk++){
            float4 a4=*(const float4*)&As[kk*68+tm*4];
            float4 b4=*(const float4*)&Bs[kk*68+tn*4];
            float av[4]={a4.x,a4.y,a4.z,a4.w},bv[4]={b4.x,b4.y,b4.z,b4.w};
#pragma unroll
            for(int i=0;i<4;i++)
#pragma unroll
                for(int j=0;j<4;j++)acc[i][j]+=av[i]*bv[j];
        }
        __syncthreads();
    }
#pragma unroll
    for(int i=0;i<4;i++){int m=m0+tm*4+i;if(m>=Mm)continue;
#pragma unroll
        for(int j=0;j<4;j++){int n=n0+tn*4+j;if(n>=Nn)continue;
            float v=acc[i][j];if(HASBIAS)v+=bias[n];if(RELU)v=fmaxf(v,0.f);
            C[(size_t)m*Nn+n]=v;}}
}

// ---- flash: fp16 1-combo S/O, online max, cp.async 2-buf (R14 champion, frozen) ----
#define SQH 0
#define SKB 67584
#define KTB 16896
#define SVB (SKB+2*KTB)
#define FL_SMEM (SVB+2*KTB)
__global__ __launch_bounds__(256,1) void flash_mma(){
    extern __shared__ __align__(16) char smem[];
    f16* sQH=(f16*)(smem+SQH);
    const int tid=threadIdx.x,wid=tid>>5,lane=tid&31;
    const int r=lane>>2,cq=(lane&3)*2;
    const int row0=blockIdx.x*128,half=blockIdx.y,kb0=half*(NB/2);
    const int a_ro=(lane&7)+((lane>>3)&1)*8,a_ch=((lane>>4)&1)*8;
    const int b_no=(lane&7)+((lane>>4)&1)*8,b_kh=((lane>>3)&1)*8;
    const int v_ro=(lane&7)+((lane>>3)&1)*8,v_co=((lane>>4)&1)*8;

    float m0=-1e30f,m1=-1e30f;
#pragma unroll
    for(int i=0;i<16;i++){
        int idx=tid+i*256,row=idx>>5,c8=(idx&31)*8;
        *(uint4*)(sQH+row*264+c8)=*(const uint4*)(g_Q16+(size_t)(row0+row)*HD+c8);
    }
    const uint32_t qh_a=smaddr(sQH+(wid*16+a_ro)*264+a_ch);
    float Oc[32][4];
#pragma unroll
    for(int t=0;t<32;t++){Oc[t][0]=0.f;Oc[t][1]=0.f;Oc[t][2]=0.f;Oc[t][3]=0.f;}
    float l0=0.f,l1=0.f;
    {
        f16* kd=(f16*)(smem+SKB);f16* vd=(f16*)(smem+SVB);
#pragma unroll
        for(int i=0;i<4;i++){
            int idx=tid+i*256,row=idx>>5,c8=(idx&31)*8;
            cpa16(smaddr(kd+row*264+c8),g_K16+(size_t)(kb0+row)*HD+c8);
            cpa16(smaddr(vd+row*264+c8),g_V16+(size_t)(kb0+row)*HD+c8);
        }
    }
    CP_COMMIT();
    for(int kt=0;kt<128;kt++){
        __syncthreads();
        if(kt+1<128){
            int buf=(kt+1)&1,kb=kb0+(kt+1)*32;
            f16* kd=(f16*)(smem+SKB+buf*KTB);f16* vd=(f16*)(smem+SVB+buf*KTB);
#pragma unroll
            for(int i=0;i<4;i++){
                int idx=tid+i*256,row=idx>>5,c8=(idx&31)*8;
                cpa16(smaddr(kd+row*264+c8),g_K16+(size_t)(kb+row)*HD+c8);
                cpa16(smaddr(vd+row*264+c8),g_V16+(size_t)(kb+row)*HD+c8);
            }
        }
        CP_COMMIT();
        CP_WAIT1();
        __syncthreads();
        const int buf=kt&1;
        const uint32_t kh_b=smaddr((f16*)(smem+SKB+buf*KTB)+b_no*264+b_kh);
        const uint32_t vh_b=smaddr((f16*)(smem+SVB+buf*KTB)+v_ro*264+v_co);
        float sv[4][4];
#pragma unroll
        for(int t=0;t<4;t++){sv[t][0]=0.f;sv[t][1]=0.f;sv[t][2]=0.f;sv[t][3]=0.f;}
#pragma unroll
        for(int ks=0;ks<16;ks++){
            uint32_t aH[4];
            ldsm4(aH,qh_a+ks*32);
#pragma unroll
            for(int tp=0;tp<2;tp++){
                uint32_t bH[4];
                ldsm4(bH,kh_b+tp*8448+ks*32);
                mma_f16(sv[tp*2],aH[0],aH[1],aH[2],aH[3],bH[0],bH[1]);
                mma_f16(sv[tp*2+1],aH[0],aH[1],aH[2],aH[3],bH[2],bH[3]);
            }
        }
        float tm0=-1e30f,tm1=-1e30f;
#pragma unroll
        for(int t=0;t<4;t++){
            tm0=fmaxf(tm0,fmaxf(sv[t][0],sv[t][1]));
            tm1=fmaxf(tm1,fmaxf(sv[t][2],sv[t][3]));
        }
        tm0=fmaxf(tm0,__shfl_xor_sync(0xffffffffu,tm0,1));
        tm0=fmaxf(tm0,__shfl_xor_sync(0xffffffffu,tm0,2));
        tm1=fmaxf(tm1,__shfl_xor_sync(0xffffffffu,tm1,1));
        tm1=fmaxf(tm1,__shfl_xor_sync(0xffffffffu,tm1,2));
        float mn0=fmaxf(m0,tm0),mn1=fmaxf(m1,tm1);
        float f0=__expf(m0-mn0),f1=__expf(m1-mn1);
        m0=mn0;m1=mn1;
        if(f0!=1.0f||f1!=1.0f){
            l0*=f0;l1*=f1;
#pragma unroll
            for(int t=0;t<32;t++){Oc[t][0]*=f0;Oc[t][1]*=f0;Oc[t][2]*=f1;Oc[t][3]*=f1;}
        }
        uint32_t pH[2][4];
        float rs0=0.f,rs1=0.f;
#pragma unroll
        for(int t=0;t<4;t++){
            float e0=__expf(sv[t][0]-m0),e1=__expf(sv[t][1]-m0);
            float e2=__expf(sv[t][2]-m1),e3=__expf(sv[t][3]-m1);
            rs0+=e0+e1;rs1+=e2+e3;
            int ksp=t>>1,h2=(t&1)*2;
            pH[ksp][h2]=packh(__float2half(e0*PSCL),__float2half(e1*PSCL));
            pH[ksp][h2+1]=packh(__float2half(e2*PSCL),__float2half(e3*PSCL));
        }
        rs0+=__shfl_xor_sync(0xffffffffu,rs0,1);rs0+=__shfl_xor_sync(0xffffffffu,rs0,2);
        rs1+=__shfl_xor_sync(0xffffffffu,rs1,1);rs1+=__shfl_xor_sync(0xffffffffu,rs1,2);
        l0+=rs0;l1+=rs1;
#pragma unroll
        for(int ks2=0;ks2<2;ks2++)
#pragma unroll
        for(int tp=0;tp<16;tp++){
            uint32_t bH[4];
            ldsm4t(bH,vh_b+ks2*8448+tp*32);
            mma_f16(Oc[tp*2],pH[ks2][0],pH[ks2][1],pH[ks2][2],pH[ks2][3],bH[0],bH[1]);
            mma_f16(Oc[tp*2+1],pH[ks2][0],pH[ks2][1],pH[ks2][2],pH[ks2][3],bH[2],bH[3]);
        }
    }
    {
        int rg=row0+wid*16+r;
        float* O=g_Opart+(size_t)half*NB*HD;
#pragma unroll
        for(int t=0;t<32;t++){
            int col=t*8+cq;
            O[(size_t)rg*HD+col]=Oc[t][0];O[(size_t)rg*HD+col+1]=Oc[t][1];
            O[(size_t)(rg+8)*HD+col]=Oc[t][2];O[(size_t)(rg+8)*HD+col+1]=Oc[t][3];
        }
        if((lane&3)==0){
            g_lpart[half*NB+rg]=l0;g_lpart[half*NB+rg+8]=l1;
            g_mpart[half*NB+rg]=m0;g_mpart[half*NB+rg+8]=m1;
        }
    }
}
__global__ void flash_merge_k(){
    int row=blockIdx.x,c=threadIdx.x;
    float ma=g_mpart[row],mb=g_mpart[NB+row];
    float m=fmaxf(ma,mb);
    float wa=__expf(ma-m),wb=__expf(mb-m);
    float denom=(g_lpart[row]*wa+g_lpart[NB+row]*wb)*PSCL;
    size_t o=(size_t)row*HD+c;
    float v=(g_Opart[o]*wa+g_Opart[(size_t)NB*HD+o]*wb)/denom;
    f16 h,l;splith(v,h,l);
    g_avhi[o]=h;g_avlo[o]=l;
}

// ---- atom self-attn + LN (stride 137) ----
#define ATP 137
#define AT_SMEM_FLOATS (4*64*ATP+64*64+512+128)
__global__ __launch_bounds__(256,1) void atom_attn_ln_k(const float* __restrict__ xg,
    const float* __restrict__ gw,const float* __restrict__ bw){
    extern __shared__ float smf[];
    float* sx=smf;float* sq=sx+64*ATP;float* sk=sq+64*ATP;float* sv=sk+64*ATP;
    float* ss=sv+64*ATP;float* sred=ss+4096;float* srow=sred+512;
    const int tid=threadIdx.x,base=blockIdx.x*64;
    for(int idx=tid;idx<64*FDIM;idx+=256){
        int a=idx/FDIM,f=idx-a*FDIM;
        sx[a*ATP+f]=xg[(size_t)(base+a)*FDIM+f];
        size_t go=(size_t)(base+a)*N3+f;
        sq[a*ATP+f]=g_qkv[go];sk[a*ATP+f]=g_qkv[go+FDIM];sv[a*ATP+f]=g_qkv[go+2*FDIM];
    }
    __syncthreads();
    {
        int ty=tid>>4,tx=tid&15;float acc[4][4]={};
        for(int h=0;h<FDIM;h++){
            float qv[4],kv[4];
#pragma unroll
            for(int i=0;i<4;i++){qv[i]=sq[(ty*4+i)*ATP+h];kv[i]=sk[(tx*4+i)*ATP+h];}
#pragma unroll
            for(int i=0;i<4;i++)
#pragma unroll
                for(int j=0;j<4;j++)acc[i][j]+=qv[i]*kv[j];
        }
        float scl=rsqrtf(133.0f);
#pragma unroll
        for(int i=0;i<4;i++)
#pragma unroll
            for(int j=0;j<4;j++)ss[(ty*4+i)*64+tx*4+j]=acc[i][j]*scl;
    }
    __syncthreads();
    if(tid<64){
        float mx=-1e30f;
        for(int j=0;j<64;j++)mx=fmaxf(mx,ss[tid*64+j]);
        float s=0.f;
        for(int j=0;j<64;j++){float e=__expf(ss[tid*64+j]-mx);ss[tid*64+j]=e;s+=e;}
        float inv=1.f/s;
        for(int j=0;j<64;j++)ss[tid*64+j]*=inv;
    }
    __syncthreads();
    const int r=tid>>2,qd=tid&3,f0=qd*34;
    float tv[34];
#pragma unroll
    for(int f=0;f<34;f++)tv[f]=0.f;
    for(int b=0;b<64;b++){
        float p=ss[r*64+b];const float* vb=&sv[b*ATP+f0];
#pragma unroll
        for(int f=0;f<34;f++)if(f0+f<FDIM)tv[f]+=p*vb[f];
    }
    float s1=0.f;
#pragma unroll
    for(int f=0;f<34;f++)if(f0+f<FDIM){tv[f]+=sx[r*ATP+f0+f];s1+=tv[f];}
    sred[tid]=s1;__syncthreads();
    if(qd==0)srow[r]=(sred[tid]+sred[tid+1]+sred[tid+2]+sred[tid+3])*(1.f/133.f);
    __syncthreads();
    float mu=srow[r],s2=0.f;
#pragma unroll
    for(int f=0;f<34;f++)if(f0+f<FDIM){float d=tv[f]-mu;s2+=d*d;}
    sred[tid]=s2;__syncthreads();
    if(qd==0){float var=(sred[tid]+sred[tid+1]+sred[tid+2]+sred[tid+3])*(1.f/133.f);srow[64+r]=rsqrtf(var+1e-5f);}
    __syncthreads();
    float rstd=srow[64+r];
#pragma unroll
    for(int f=0;f<34;f++){int fg=f0+f;
        if(fg<FDIM)g_fe[(size_t)(base+r)*FDIM+fg]=(tv[f]-mu)*rstd*gw[fg]+bw[fg];}
}

__global__ void gather_sum_k(const int* __restrict__ a2b){
    __shared__ int idx[MAXNB];
    int a=blockIdx.x,t=threadIdx.x;
    if(t<MAXNB)idx[t]=a2b[a*MAXNB+t];
    __syncthreads();
    float s=0.f;
#pragma unroll
    for(int j=0;j<MAXNB;j++)s+=g_msg[(size_t)idx[j]*HD+t];
    g_amsg[(size_t)a*HD+t]=s;
}
// parallel index loads (threads 0..6), same barrier structure
__global__ void dmpnn_fused_k(const int* __restrict__ a2b,const int* __restrict__ b2a,
    const int* __restrict__ b2revb){
    __shared__ int idx[MAXNB+1];
    __shared__ int sia;
    int b=blockIdx.x,t=threadIdx.x;
    if(t==0)sia=__ldg(&b2a[b]);
    if(t==MAXNB)idx[MAXNB]=__ldg(&b2revb[b]);
    __syncthreads();
    if(t<MAXNB)idx[t]=__ldg(&a2b[sia*MAXNB+t]);
    __syncthreads();
    float s=0.f;
#pragma unroll
    for(int j=0;j<MAXNB;j++)s+=g_msg[(size_t)idx[j]*HD+t];
    float v=s-g_msg[(size_t)idx[MAXNB]*HD+t];
    f16 h,l;splith(v,h,l);
    size_t o=(size_t)b*HD+t;
    g_tmphi[o]=h;g_tmplo[o]=l;
}
// shuffle-based reduction (2 barriers instead of 8)
__global__ void combine_k(const float* __restrict__ wal,const float* __restrict__ walb){
    __shared__ float wred[8];
    __shared__ float salpha;
    int b=blockIdx.x,t=threadIdx.x,lane=t&31,w=t>>5;
    size_t o=(size_t)b*HD+t;
    float d=g_dmpnn[o],am=g_attm[o];
    float x=d*wal[t]+am*wal[256+t];
#pragma unroll
    for(int sft=16;sft>0;sft>>=1)x+=__shfl_xor_sync(0xffffffffu,x,sft);
    if(lane==0)wred[w]=x;
    __syncthreads();
    if(t==0){
        float s=wred[0]+wred[1]+wred[2]+wred[3]+wred[4]+wred[5]+wred[6]+wred[7];
        salpha=1.f/(1.f+__expf(-(s+walb[0])));
    }
    __syncthreads();
    float al=salpha;
    float v=fmaxf(g_inputs[o]+al*d+(1.f-al)*am,0.f);
    g_msg[o]=v;
    f16 h,l;splith(v,h,l);
    g_msghi[o]=h;g_msglo[o]=l;
}
__global__ void concat_split_k(){
    int i=blockIdx.x*blockDim.x+threadIdx.x;
    if(i>=NA*KP_WO)return;
    int row=i/KP_WO,c=i-row*KP_WO;
    float x=(c<FDIM)?g_fe[(size_t)row*FDIM+c]:(c<FDIM+HD?g_amsg[(size_t)row*HD+(c-FDIM)]:0.f);
    f16 h,l;splith(x,h,l);
    g_cathi[i]=h;g_catlo[i]=l;
}

#define MP_SMEM_FLOATS (2*64*260+4096)
__global__ __launch_bounds__(256,1) void mol_pool_k(const float* __restrict__ Wb,
    const float* __restrict__ bb,float* __restrict__ outg){
    extern __shared__ float smf[];
    float* shm=smf;float* sw=shm+64*260;float* ssc=sw+64*260;
    const int tid=threadIdx.x,base=blockIdx.x*64;
    for(int idx=tid;idx<64*HD;idx+=256){
        int a=idx>>8,c=idx&255;
        shm[a*260+c]=g_atomh[(size_t)(base+a)*HD+c];
        sw[a*260+c]=g_hmwa[(size_t)(base+a)*HD+c];
    }
    __syncthreads();
    {
        int ty=tid>>4,tx=tid&15;float acc[4][4]={};
        for(int h=0;h<HD;h++){
            float qv[4],kv[4];
#pragma unroll
            for(int i=0;i<4;i++){qv[i]=sw[(ty*4+i)*260+h];kv[i]=shm[(tx*4+i)*260+h];}
#pragma unroll
            for(int i=0;i<4;i++)
#pragma unroll
                for(int j=0;j<4;j++)acc[i][j]+=qv[i]*kv[j];
        }
#pragma unroll
        for(int i=0;i<4;i++)
#pragma unroll
            for(int j=0;j<4;j++)ssc[(ty*4+i)*64+tx*4+j]=acc[i][j];
    }
    __syncthreads();
    if(tid<64){
        float mx=-1e30f;
        for(int j=0;j<64;j++)mx=fmaxf(mx,ssc[tid*64+j]);
        float s=0.f;
        for(int j=0;j<64;j++){float e=__expf(ssc[tid*64+j]-mx);ssc[tid*64+j]=e;s+=e;}
        float inv=1.f/s;
        for(int j=0;j<64;j++)ssc[tid*64+j]*=inv;
    }
    __syncthreads();
    const int c=tid;
    float acc[64];
#pragma unroll
    for(int a=0;a<64;a++)acc[a]=0.f;
    for(int b=0;b<64;b++){
        float hv=shm[b*260+c];
#pragma unroll 16
        for(int a=0;a<64;a++)acc[a]+=ssc[a*64+b]*hv;
    }
    __syncthreads();
    for(int a=0;a<64;a++)sw[a*260+c]=acc[a];
    __syncthreads();
#pragma unroll
    for(int a=0;a<64;a++)acc[a]=0.f;
    for(int k=0;k<HD;k++){
        float wv=Wb[(size_t)k*HD+c];
#pragma unroll 16
        for(int a=0;a<64;a++)acc[a]+=sw[a*260+k]*wv;
    }
    float bv=bb[c],s=0.f;
    for(int a=0;a<64;a++){float t=fmaxf(acc[a]+bv,0.f);s+=shm[a*260+c]+t;}
    outg[(size_t)blockIdx.x*HD+c]=s*(1.f/64.f);
}

static float* symf(const void* s){void* p=nullptr;cudaGetSymbolAddress(&p,s);return (float*)p;}
static f16* symh(const void* s){void* p=nullptr;cudaGetSymbolAddress(&p,s);return (f16*)p;}

extern "C" void kernel_launch(void* const* d_in,const int* in_sizes,int n_in,void* d_out,int out_size){
    const float* f_atoms=(const float*)d_in[0];
    const float* f_bonds=(const float*)d_in[1];
    const float* Wq_atom=(const float*)d_in[2];
    const float* Wk_atom=(const float*)d_in[3];
    const float* Wv_atom=(const float*)d_in[4];
    const float* ln_g=(const float*)d_in[5];
    const float* ln_b=(const float*)d_in[6];
    const float* Wi=(const float*)d_in[7];
    const float* Wh=(const float*)d_in[8];
    const float* Wq=(const float*)d_in[9];
    const float* Wk=(const float*)d_in[10];
    const float* Wv=(const float*)d_in[11];
    const float* Wa=(const float*)d_in[12];
    const float* Walw=(const float*)d_in[13];
    const float* Walb=(const float*)d_in[14];
    const float* Wow=(const float*)d_in[15];
    const float* Wob=(const float*)d_in[16];
    const float* Wbw=(const float*)d_in[17];
    const float* Wbb=(const float*)d_in[18];
    const int* a2b=(const int*)d_in[19];
    const int* b2a=(const int*)d_in[20];
    const int* b2revb=(const int*)d_in[21];
    float* out=(float*)d_out;

    float* p_W3=symf(g_W3);float* p_qkv=symf(g_qkv);
    float* p_inputs=symf(g_inputs);float* p_msg=symf(g_msg);
    float* p_dmpnn=symf(g_dmpnn);float* p_attm=symf(g_attm);
    float* p_atomh=symf(g_atomh);float* p_hmwa=symf(g_hmwa);
    f16* p_Q16=symh(g_Q16);f16* p_K16=symh(g_K16);f16* p_V16=symh(g_V16);
    f16* p_msghi=symh(g_msghi);f16* p_msglo=symh(g_msglo);
    f16* p_tmphi=symh(g_tmphi);f16* p_tmplo=symh(g_tmplo);
    f16* p_avhi=symh(g_avhi);f16* p_avlo=symh(g_avlo);
    f16* p_fbhi=symh(g_fbhi);f16* p_fblo=symh(g_fblo);
    f16* p_cathi=symh(g_cathi);f16* p_catlo=symh(g_catlo);
    f16* p_ahhi=symh(g_ahhi);f16* p_ahlo=symh(g_ahlo);
    f16* p_Withi=symh(g_Withi);f16* p_Witlo=symh(g_Witlo);
    f16* p_Whthi=symh(g_Whthi);f16* p_Whtlo=symh(g_Whtlo);
    f16* p_Wqkvthi=symh(g_Wqkvthi);f16* p_Wqkvtlo=symh(g_Wqkvtlo);
    f16* p_Wathi=symh(g_Wathi);f16* p_Watlo=symh(g_Watlo);
    f16* p_Wothi=symh(g_Wothi);f16* p_Wotlo=symh(g_Wotlo);

    const int AT_SMEM=AT_SMEM_FLOATS*4,MP_SMEM=MP_SMEM_FLOATS*4;
    cudaFuncSetAttribute(flash_mma,cudaFuncAttributeMaxDynamicSharedMemorySize,FL_SMEM);
    cudaFuncSetAttribute(atom_attn_ln_k,cudaFuncAttributeMaxDynamicSharedMemorySize,AT_SMEM);
    cudaFuncSetAttribute(mol_pool_k,cudaFuncAttributeMaxDynamicSharedMemorySize,MP_SMEM);
    cudaFuncSetAttribute(tgemm<1,0,0,1,1,1,0,0>,cudaFuncAttributeMaxDynamicSharedMemorySize,TG_SMEM);
    cudaFuncSetAttribute(tgemm<0,0,0,1,0,0,0,0>,cudaFuncAttributeMaxDynamicSharedMemorySize,TG_SMEM);
    cudaFuncSetAttribute(tgemm<0,0,0,0,0,0,0,1>,cudaFuncAttributeMaxDynamicSharedMemorySize,TG_SMEM);
    cudaFuncSetAttribute(tgemm<1,1,0,1,1,0,0,0>,cudaFuncAttributeMaxDynamicSharedMemorySize,TG_SMEM);

    const int WALL=SZ_WI+5*SZ_H+SZ_WO;
    wsplit_all_k<<<(WALL+255)/256,256>>>(Wi,Wh,Wq,Wk,Wv,Wa,Wow);
    asplit_k<<<(NB*KP_WI)/256,256>>>(f_bonds,p_fbhi,p_fblo,BFDIM,KP_WI);
    w3copy_k<<<(FDIM*N3+255)/256,256>>>(Wq_atom,Wk_atom,Wv_atom);

    dim3 gqa((N3+63)/64,(NA+63)/64);
    gemm_k<0,0><<<gqa,256>>>(f_atoms,p_W3,nullptr,p_qkv,NA,N3,FDIM);
    atom_attn_ln_k<<<NMOL,256,AT_SMEM>>>(f_atoms,ln_g,ln_b);

    dim3 tgb(4,NB/128),tga(4,NA/128),tgqkv(12,NB/128);
    tgemm<1,0,0,1,1,1,0,0><<<tgb,256,TG_SMEM>>>(p_fbhi,p_fblo,p_Withi,p_Witlo,nullptr,
        p_msg,p_msghi,p_msglo,nullptr,p_inputs,NB,KP_WI);

    for(int it=0;it<3;it++){
        dmpnn_fused_k<<<NB,256>>>(a2b,b2a,b2revb);
        tgemm<0,0,0,1,0,0,0,0><<<tgb,256,TG_SMEM>>>(p_tmphi,p_tmplo,p_Whthi,p_Whtlo,nullptr,
            p_dmpnn,nullptr,nullptr,nullptr,nullptr,NB,HD);
        tgemm<0,0,0,0,0,0,0,1><<<tgqkv,256,TG_SMEM>>>(p_msghi,p_msglo,p_Wqkvthi,p_Wqkvtlo,nullptr,
            nullptr,p_Q16,p_K16,p_V16,nullptr,NB,HD);
        flash_mma<<<dim3(NB/128,2),256,FL_SMEM>>>();
        flash_merge_k<<<NB,256>>>();
        tgemm<0,0,0,1,0,0,0,0><<<tgb,256,TG_SMEM>>>(p_avhi,p_avlo,p_Wathi,p_Watlo,nullptr,
            p_attm,nullptr,nullptr,nullptr,nullptr,NB,HD);
        combine_k<<<NB,256>>>(Walw,Walb);
    }

    gather_sum_k<<<NA,256>>>(a2b);
    concat_split_k<<<(NA*KP_WO+255)/256,256>>>();
    tgemm<1,1,0,1,1,0,0,0><<<tga,256,TG_SMEM>>>(p_cathi,p_catlo,p_Wothi,p_Wotlo,Wob,
        p_atomh,p_ahhi,p_ahlo,nullptr,nullptr,NA,KP_WO);
    tgemm<0,0,0,1,0,0,0,0><<<tga,256,TG_SMEM>>>(p_ahhi,p_ahlo,p_Wathi,p_Watlo,nullptr,
        p_hmwa,nullptr,nullptr,nullptr,nullptr,NA,HD);
    mol_pool_k<<<NMOL,256,MP_SMEM>>>(Wbw,Wbb,out);
}

// round 17
// speedup vs baseline: 1.0668x; 1.0151x over previous
#include <cuda_runtime.h>
#include <cuda_fp16.h>
#include <math.h>
#include <stdint.h>
#define NA 4096
#define NB 8192
#define FDIM 133
#define BFDIM 147
#define HD 256
#define NMOL 64
#define MAXNB 6
#define KP_WI 160
#define KP_WO 416
#define KP_A3 160
#define N3P 448
#define LOSCL 2048.0f
#define INVLO (1.0f/2048.0f)
#define PSCL 1024.0f
typedef __half f16;

__device__ __align__(16) float g_qkv[NA*N3P];
__device__ __align__(16) float g_fe[NA*FDIM];
__device__ __align__(16) float g_inputs[NB*HD];
__device__ __align__(16) float g_msg[NB*HD];
__device__ __align__(16) float g_amsg[NA*HD];
__device__ __align__(16) float g_dmpnn[NB*HD];
__device__ __align__(16) float g_attm[NB*HD];
__device__ __align__(16) float g_atomh[NA*HD];
__device__ __align__(16) float g_hmwa[NA*HD];
__device__ __align__(16) float g_Opart[2*NB*HD];
__device__ __align__(16) float g_lpart[2*NB];
__device__ __align__(16) float g_mpart[2*NB];
__device__ __align__(16) f16 g_Q16[NB*HD];
__device__ __align__(16) f16 g_K16[NB*HD];
__device__ __align__(16) f16 g_V16[NB*HD];
__device__ __align__(16) f16 g_msghi[NB*HD];
__device__ __align__(16) f16 g_msglo[NB*HD];
__device__ __align__(16) f16 g_tmphi[NB*HD];
__device__ __align__(16) f16 g_tmplo[NB*HD];
__device__ __align__(16) f16 g_avhi[NB*HD];
__device__ __align__(16) f16 g_avlo[NB*HD];
__device__ __align__(16) f16 g_fbhi[NB*KP_WI];
__device__ __align__(16) f16 g_fblo[NB*KP_WI];
__device__ __align__(16) f16 g_fahi[NA*KP_A3];
__device__ __align__(16) f16 g_falo[NA*KP_A3];
__device__ __align__(16) f16 g_cathi[NA*KP_WO];
__device__ __align__(16) f16 g_catlo[NA*KP_WO];
__device__ __align__(16) f16 g_ahhi[NA*HD];
__device__ __align__(16) f16 g_ahlo[NA*HD];
__device__ __align__(16) f16 g_Withi[HD*KP_WI];
__device__ __align__(16) f16 g_Witlo[HD*KP_WI];
__device__ __align__(16) f16 g_Whthi[HD*HD];
__device__ __align__(16) f16 g_Whtlo[HD*HD];
__device__ __align__(16) f16 g_Wqkvthi[3*HD*HD];
__device__ __align__(16) f16 g_Wqkvtlo[3*HD*HD];
__device__ __align__(16) f16 g_Wathi[HD*HD];
__device__ __align__(16) f16 g_Watlo[HD*HD];
__device__ __align__(16) f16 g_Wothi[HD*KP_WO];
__device__ __align__(16) f16 g_Wotlo[HD*KP_WO];
__device__ __align__(16) f16 g_W3thi[N3P*KP_A3];
__device__ __align__(16) f16 g_W3tlo[N3P*KP_A3];

__device__ __forceinline__ void mma_f16(float* c,uint32_t a0,uint32_t a1,uint32_t a2,uint32_t a3,uint32_t b0,uint32_t b1){
    asm("mma.sync.aligned.m16n8k16.row.col.f32.f16.f16.f32 {%0,%1,%2,%3},{%4,%5,%6,%7},{%8,%9},{%0,%1,%2,%3};\n"
        :"+f"(c[0]),"+f"(c[1]),"+f"(c[2]),"+f"(c[3]):"r"(a0),"r"(a1),"r"(a2),"r"(a3),"r"(b0),"r"(b1));
}
__device__ __forceinline__ uint32_t smaddr(const void* p){return (uint32_t)__cvta_generic_to_shared(p);}
__device__ __forceinline__ void ldsm4(uint32_t* r,uint32_t a){
    asm volatile("ldmatrix.sync.aligned.m8n8.x4.shared.b16 {%0,%1,%2,%3},[%4];":"=r"(r[0]),"=r"(r[1]),"=r"(r[2]),"=r"(r[3]):"r"(a));
}
__device__ __forceinline__ void ldsm4t(uint32_t* r,uint32_t a){
    asm volatile("ldmatrix.sync.aligned.m8n8.x4.trans.shared.b16 {%0,%1,%2,%3},[%4];":"=r"(r[0]),"=r"(r[1]),"=r"(r[2]),"=r"(r[3]):"r"(a));
}
__device__ __forceinline__ void cpa16(uint32_t s,const void* g){
    asm volatile("cp.async.ca.shared.global [%0],[%1],16;\n"::"r"(s),"l"(g));
}
#define CP_COMMIT() asm volatile("cp.async.commit_group;\n":::"memory")
#define CP_WAIT1()  asm volatile("cp.async.wait_group 1;\n":::"memory")
__device__ __forceinline__ void splith(float x,f16& h,f16& l){h=__float2half(x);l=__float2half((x-__half2float(h))*LOSCL);}
__device__ __forceinline__ uint32_t packh(f16 a,f16 b){return ((uint32_t)__half_as_ushort(b)<<16)|(uint32_t)__half_as_ushort(a);}

// ---- fp16 hi/lo GEMM, 3 combos, cp.async 2-stage pipelined; ldc = C row stride ----
#define TGST 15360
#define TG_SMEM (2*TGST*2)
template <int RELU,int HASBIAS,int SCALEQ,int OUTF32,int OUTSPLIT,int PREAUX,int OUTV16,int OUTQKV>
__global__ __launch_bounds__(256,2) void tgemm(const f16* __restrict__ Ah,const f16* __restrict__ Al,
    const f16* __restrict__ Bh,const f16* __restrict__ Bl,const float* __restrict__ bias,
    float* __restrict__ Cf,f16* __restrict__ Chi,f16* __restrict__ Clo,f16* __restrict__ V16,
    float* __restrict__ Caux,int M,int K,int ldc){
    extern __shared__ __align__(16) f16 sm[];
    const int tid=threadIdx.x,wid=tid>>5,lane=tid&31;
    const int r=lane>>2,cq=(lane&3)*2,wm=wid>>1,wn=wid&1;
    const int m0=blockIdx.y*128,n0=blockIdx.x*64;
    const int a_ro=(lane&7)+((lane>>3)&1)*8,a_ch=((lane>>4)&1)*8;
    const int b_no=(lane&7)+((lane>>4)&1)*8,b_kh=((lane>>3)&1)*8;
    const int ar=tid>>2,aq=(tid&3)*8;
    const int br=tid>>2,bq=(tid&3)*8;
    float acc[2][4][4]={},acL[2][4][4]={};
    const int nch=K>>5;
    {
        f16* st=sm;
        cpa16(smaddr(st+ar*40+aq),Ah+(size_t)(m0+ar)*K+aq);
        cpa16(smaddr(st+(64+ar)*40+aq),Ah+(size_t)(m0+64+ar)*K+aq);
        cpa16(smaddr(st+5120+ar*40+aq),Al+(size_t)(m0+ar)*K+aq);
        cpa16(smaddr(st+5120+(64+ar)*40+aq),Al+(size_t)(m0+64+ar)*K+aq);
        cpa16(smaddr(st+10240+br*40+bq),Bh+(size_t)(n0+br)*K+bq);
        cpa16(smaddr(st+12800+br*40+bq),Bl+(size_t)(n0+br)*K+bq);
    }
    CP_COMMIT();
    for(int ic=0;ic<nch;ic++){
        __syncthreads();
        if(ic+1<nch){
            f16* st=sm+((ic+1)&1)*TGST;
            int kc=(ic+1)*32;
            cpa16(smaddr(st+ar*40+aq),Ah+(size_t)(m0+ar)*K+kc+aq);
            cpa16(smaddr(st+(64+ar)*40+aq),Ah+(size_t)(m0+64+ar)*K+kc+aq);
            cpa16(smaddr(st+5120+ar*40+aq),Al+(size_t)(m0+ar)*K+kc+aq);
            cpa16(smaddr(st+5120+(64+ar)*40+aq),Al+(size_t)(m0+64+ar)*K+kc+aq);
            cpa16(smaddr(st+10240+br*40+bq),Bh+(size_t)(n0+br)*K+kc+bq);
            cpa16(smaddr(st+12800+br*40+bq),Bl+(size_t)(n0+br)*K+kc+bq);
        }
        CP_COMMIT();
        CP_WAIT1();
        __syncthreads();
        f16* st=sm+(ic&1)*TGST;
        uint32_t aHb[2],aLb[2],bHb,bLb;
        aHb[0]=smaddr(st+(wm*32+a_ro)*40+a_ch);aHb[1]=smaddr(st+(wm*32+16+a_ro)*40+a_ch);
        aLb[0]=smaddr(st+5120+(wm*32+a_ro)*40+a_ch);aLb[1]=smaddr(st+5120+(wm*32+16+a_ro)*40+a_ch);
        bHb=smaddr(st+10240+(wn*32+b_no)*40+b_kh);bLb=smaddr(st+12800+(wn*32+b_no)*40+b_kh);
#pragma unroll
        for(int ks=0;ks<2;ks++){
            uint32_t aH[2][4],aL[2][4];
#pragma unroll
            for(int mf=0;mf<2;mf++){ldsm4(aH[mf],aHb[mf]+ks*32);ldsm4(aL[mf],aLb[mf]+ks*32);}
#pragma unroll
            for(int np=0;np<2;np++){
                uint32_t bH[4],bL[4];
                ldsm4(bH,bHb+np*1280+ks*32);ldsm4(bL,bLb+np*1280+ks*32);
#pragma unroll
                for(int mf=0;mf<2;mf++){
                    mma_f16(acc[mf][np*2],aH[mf][0],aH[mf][1],aH[mf][2],aH[mf][3],bH[0],bH[1]);
                    mma_f16(acL[mf][np*2],aL[mf][0],aL[mf][1],aL[mf][2],aL[mf][3],bH[0],bH[1]);
                    mma_f16(acL[mf][np*2],aH[mf][0],aH[mf][1],aH[mf][2],aH[mf][3],bL[0],bL[1]);
                    mma_f16(acc[mf][np*2+1],aH[mf][0],aH[mf][1],aH[mf][2],aH[mf][3],bH[2],bH[3]);
                    mma_f16(acL[mf][np*2+1],aL[mf][0],aL[mf][1],aL[mf][2],aL[mf][3],bH[2],bH[3]);
                    mma_f16(acL[mf][np*2+1],aH[mf][0],aH[mf][1],aH[mf][2],aH[mf][3],bL[2],bL[3]);
                }
            }
        }
    }
#pragma unroll
    for(int mf=0;mf<2;mf++)
#pragma unroll
    for(int nf=0;nf<4;nf++){
        int mrow=m0+wm*32+mf*16+r,col=n0+wn*32+nf*8+cq;
        float c0=acc[mf][nf][0]+acL[mf][nf][0]*INVLO,c1=acc[mf][nf][1]+acL[mf][nf][1]*INVLO;
        float c2=acc[mf][nf][2]+acL[mf][nf][2]*INVLO,c3=acc[mf][nf][3]+acL[mf][nf][3]*INVLO;
        if(HASBIAS){float b0=bias[col],b1=bias[col+1];c0+=b0;c1+=b1;c2+=b0;c3+=b1;}
        if(SCALEQ){c0*=0.0625f;c1*=0.0625f;c2*=0.0625f;c3*=0.0625f;}
        if(PREAUX){Caux[(size_t)mrow*ldc+col]=c0;Caux[(size_t)mrow*ldc+col+1]=c1;
            Caux[(size_t)(mrow+8)*ldc+col]=c2;Caux[(size_t)(mrow+8)*ldc+col+1]=c3;}
        if(RELU){c0=fmaxf(c0,0.f);c1=fmaxf(c1,0.f);c2=fmaxf(c2,0.f);c3=fmaxf(c3,0.f);}
        if(OUTF32){Cf[(size_t)mrow*ldc+col]=c0;Cf[(size_t)mrow*ldc+col+1]=c1;
            Cf[(size_t)(mrow+8)*ldc+col]=c2;Cf[(size_t)(mrow+8)*ldc+col+1]=c3;}
        if(OUTSPLIT){f16 h0,l0,h1,l1,h2,l2,h3,l3;
            splith(c0,h0,l0);splith(c1,h1,l1);splith(c2,h2,l2);splith(c3,h3,l3);
            *(uint32_t*)(Chi+(size_t)mrow*HD+col)=packh(h0,h1);
            *(uint32_t*)(Clo+(size_t)mrow*HD+col)=packh(l0,l1);
            *(uint32_t*)(Chi+(size_t)(mrow+8)*HD+col)=packh(h2,h3);
            *(uint32_t*)(Clo+(size_t)(mrow+8)*HD+col)=packh(l2,l3);}
        if(OUTV16){
            *(uint32_t*)(V16+(size_t)mrow*HD+col)=packh(__float2half(c0),__float2half(c1));
            *(uint32_t*)(V16+(size_t)(mrow+8)*HD+col)=packh(__float2half(c2),__float2half(c3));}
        if(OUTQKV){
            int seg=col>>8,cl=col&255;
            f16* dst=(seg==0)?Chi:((seg==1)?Clo:V16);
            float sc=(seg==0)?0.0625f:1.f;
            *(uint32_t*)(dst+(size_t)mrow*HD+cl)=packh(__float2half(c0*sc),__float2half(c1*sc));
            *(uint32_t*)(dst+(size_t)(mrow+8)*HD+cl)=packh(__float2half(c2*sc),__float2half(c3*sc));}
    }
}

#define SZ_WI (HD*KP_WI)
#define SZ_H  (HD*HD)
#define SZ_WO (HD*KP_WO)
#define SZ_W3 (N3P*KP_A3)
__global__ void wsplit_all_k(const float* __restrict__ Wi,const float* __restrict__ Wh,
    const float* __restrict__ Wq,const float* __restrict__ Wk,const float* __restrict__ Wv,
    const float* __restrict__ Wa,const float* __restrict__ Wo,
    const float* __restrict__ Wqa,const float* __restrict__ Wka,const float* __restrict__ Wva){
    int idx=blockIdx.x*blockDim.x+threadIdx.x;
    if(idx>=SZ_WI+SZ_H){
        if(idx<SZ_WI+4*SZ_H){
            int local=idx-SZ_WI-SZ_H,n=local>>8,k=local&255;
            const float* W=(n<256)?Wq:((n<512)?Wk:Wv);
            float x=W[(size_t)k*HD+(n&255)];
            f16 h,l;splith(x,h,l);
            g_Wqkvthi[local]=h;g_Wqkvtlo[local]=l;return;
        }
        if(idx<SZ_WI+5*SZ_H){
            int local=idx-SZ_WI-4*SZ_H,k=local&255,n=local>>8;
            float x=Wa[(size_t)k*HD+n];
            f16 h,l;splith(x,h,l);g_Wathi[local]=h;g_Watlo[local]=l;return;
        }
        if(idx<SZ_WI+5*SZ_H+SZ_WO){
            int local=idx-SZ_WI-5*SZ_H,k=local%KP_WO,n=local/KP_WO;
            float x=(k<FDIM+HD)?Wo[(size_t)k*HD+n]:0.f;
            f16 h,l;splith(x,h,l);g_Wothi[local]=h;g_Wotlo[local]=l;return;
        }
        if(idx<SZ_WI+5*SZ_H+SZ_WO+SZ_W3){
            int local=idx-SZ_WI-5*SZ_H-SZ_WO,k=local%KP_A3,n=local/KP_A3;
            float x=0.f;
            if(k<FDIM){
                if(n<FDIM)x=Wqa[(size_t)k*FDIM+n];
                else if(n<2*FDIM)x=Wka[(size_t)k*FDIM+(n-FDIM)];
                else if(n<3*FDIM)x=Wva[(size_t)k*FDIM+(n-2*FDIM)];
            }
            f16 h,l;splith(x,h,l);g_W3thi[local]=h;g_W3tlo[local]=l;return;
        }
        return;
    }
    if(idx<SZ_WI){
        int k=idx%KP_WI,n=idx/KP_WI;
        float x=(k<BFDIM)?Wi[(size_t)k*HD+n]:0.f;
        f16 h,l;splith(x,h,l);g_Withi[idx]=h;g_Witlo[idx]=l;return;
    }
    {
        int local=idx-SZ_WI,k=local&255,n=local>>8;
        float x=Wh[(size_t)k*HD+n];
        f16 h,l;splith(x,h,l);g_Whthi[local]=h;g_Whtlo[local]=l;
    }
}
__global__ void asplit_k(const float* __restrict__ A,f16* __restrict__ hi,f16* __restrict__ lo,int K,int KPp){
    int idx=blockIdx.x*blockDim.x+threadIdx.x;
    int k=idx%KPp,m=idx/KPp;
    float x=(k<K)?A[(size_t)m*K+k]:0.f;
    f16 h,l;splith(x,h,l);hi[idx]=h;lo[idx]=l;
}

// ---- flash: fp16 1-combo S/O, online max, cp.async 2-buf (R14 champion, frozen) ----
#define SQH 0
#define SKB 67584
#define KTB 16896
#define SVB (SKB+2*KTB)
#define FL_SMEM (SVB+2*KTB)
__global__ __launch_bounds__(256,1) void flash_mma(){
    extern __shared__ __align__(16) char smem[];
    f16* sQH=(f16*)(smem+SQH);
    const int tid=threadIdx.x,wid=tid>>5,lane=tid&31;
    const int r=lane>>2,cq=(lane&3)*2;
    const int row0=blockIdx.x*128,half=blockIdx.y,kb0=half*(NB/2);
    const int a_ro=(lane&7)+((lane>>3)&1)*8,a_ch=((lane>>4)&1)*8;
    const int b_no=(lane&7)+((lane>>4)&1)*8,b_kh=((lane>>3)&1)*8;
    const int v_ro=(lane&7)+((lane>>3)&1)*8,v_co=((lane>>4)&1)*8;

    float m0=-1e30f,m1=-1e30f;
#pragma unroll
    for(int i=0;i<16;i++){
        int idx=tid+i*256,row=idx>>5,c8=(idx&31)*8;
        *(uint4*)(sQH+row*264+c8)=*(const uint4*)(g_Q16+(size_t)(row0+row)*HD+c8);
    }
    const uint32_t qh_a=smaddr(sQH+(wid*16+a_ro)*264+a_ch);
    float Oc[32][4];
#pragma unroll
    for(int t=0;t<32;t++){Oc[t][0]=0.f;Oc[t][1]=0.f;Oc[t][2]=0.f;Oc[t][3]=0.f;}
    float l0=0.f,l1=0.f;
    {
        f16* kd=(f16*)(smem+SKB);f16* vd=(f16*)(smem+SVB);
#pragma unroll
        for(int i=0;i<4;i++){
            int idx=tid+i*256,row=idx>>5,c8=(idx&31)*8;
            cpa16(smaddr(kd+row*264+c8),g_K16+(size_t)(kb0+row)*HD+c8);
            cpa16(smaddr(vd+row*264+c8),g_V16+(size_t)(kb0+row)*HD+c8);
        }
    }
    CP_COMMIT();
    for(int kt=0;kt<128;kt++){
        __syncthreads();
        if(kt+1<128){
            int buf=(kt+1)&1,kb=kb0+(kt+1)*32;
            f16* kd=(f16*)(smem+SKB+buf*KTB);f16* vd=(f16*)(smem+SVB+buf*KTB);
#pragma unroll
            for(int i=0;i<4;i++){
                int idx=tid+i*256,row=idx>>5,c8=(idx&31)*8;
                cpa16(smaddr(kd+row*264+c8),g_K16+(size_t)(kb+row)*HD+c8);
                cpa16(smaddr(vd+row*264+c8),g_V16+(size_t)(kb+row)*HD+c8);
            }
        }
        CP_COMMIT();
        CP_WAIT1();
        __syncthreads();
        const int buf=kt&1;
        const uint32_t kh_b=smaddr((f16*)(smem+SKB+buf*KTB)+b_no*264+b_kh);
        const uint32_t vh_b=smaddr((f16*)(smem+SVB+buf*KTB)+v_ro*264+v_co);
        float sv[4][4];
#pragma unroll
        for(int t=0;t<4;t++){sv[t][0]=0.f;sv[t][1]=0.f;sv[t][2]=0.f;sv[t][3]=0.f;}
#pragma unroll
        for(int ks=0;ks<16;ks++){
            uint32_t aH[4];
            ldsm4(aH,qh_a+ks*32);
#pragma unroll
            for(int tp=0;tp<2;tp++){
                uint32_t bH[4];
                ldsm4(bH,kh_b+tp*8448+ks*32);
                mma_f16(sv[tp*2],aH[0],aH[1],aH[2],aH[3],bH[0],bH[1]);
                mma_f16(sv[tp*2+1],aH[0],aH[1],aH[2],aH[3],bH[2],bH[3]);
            }
        }
        float tm0=-1e30f,tm1=-1e30f;
#pragma unroll
        for(int t=0;t<4;t++){
            tm0=fmaxf(tm0,fmaxf(sv[t][0],sv[t][1]));
            tm1=fmaxf(tm1,fmaxf(sv[t][2],sv[t][3]));
        }
        tm0=fmaxf(tm0,__shfl_xor_sync(0xffffffffu,tm0,1));
        tm0=fmaxf(tm0,__shfl_xor_sync(0xffffffffu,tm0,2));
        tm1=fmaxf(tm1,__shfl_xor_sync(0xffffffffu,tm1,1));
        tm1=fmaxf(tm1,__shfl_xor_sync(0xffffffffu,tm1,2));
        float mn0=fmaxf(m0,tm0),mn1=fmaxf(m1,tm1);
        float f0=__expf(m0-mn0),f1=__expf(m1-mn1);
        m0=mn0;m1=mn1;
        if(f0!=1.0f||f1!=1.0f){
            l0*=f0;l1*=f1;
#pragma unroll
            for(int t=0;t<32;t++){Oc[t][0]*=f0;Oc[t][1]*=f0;Oc[t][2]*=f1;Oc[t][3]*=f1;}
        }
        uint32_t pH[2][4];
        float rs0=0.f,rs1=0.f;
#pragma unroll
        for(int t=0;t<4;t++){
            float e0=__expf(sv[t][0]-m0),e1=__expf(sv[t][1]-m0);
            float e2=__expf(sv[t][2]-m1),e3=__expf(sv[t][3]-m1);
            rs0+=e0+e1;rs1+=e2+e3;
            int ksp=t>>1,h2=(t&1)*2;
            pH[ksp][h2]=packh(__float2half(e0*PSCL),__float2half(e1*PSCL));
            pH[ksp][h2+1]=packh(__float2half(e2*PSCL),__float2half(e3*PSCL));
        }
        rs0+=__shfl_xor_sync(0xffffffffu,rs0,1);rs0+=__shfl_xor_sync(0xffffffffu,rs0,2);
        rs1+=__shfl_xor_sync(0xffffffffu,rs1,1);rs1+=__shfl_xor_sync(0xffffffffu,rs1,2);
        l0+=rs0;l1+=rs1;
#pragma unroll
        for(int ks2=0;ks2<2;ks2++)
#pragma unroll
        for(int tp=0;tp<16;tp++){
            uint32_t bH[4];
            ldsm4t(bH,vh_b+ks2*8448+tp*32);
            mma_f16(Oc[tp*2],pH[ks2][0],pH[ks2][1],pH[ks2][2],pH[ks2][3],bH[0],bH[1]);
            mma_f16(Oc[tp*2+1],pH[ks2][0],pH[ks2][1],pH[ks2][2],pH[ks2][3],bH[2],bH[3]);
        }
    }
    {
        int rg=row0+wid*16+r;
        float* O=g_Opart+(size_t)half*NB*HD;
#pragma unroll
        for(int t=0;t<32;t++){
            int col=t*8+cq;
            O[(size_t)rg*HD+col]=Oc[t][0];O[(size_t)rg*HD+col+1]=Oc[t][1];
            O[(size_t)(rg+8)*HD+col]=Oc[t][2];O[(size_t)(rg+8)*HD+col+1]=Oc[t][3];
        }
        if((lane&3)==0){
            g_lpart[half*NB+rg]=l0;g_lpart[half*NB+rg+8]=l1;
            g_mpart[half*NB+rg]=m0;g_mpart[half*NB+rg+8]=m1;
        }
    }
}
__global__ void flash_merge_k(){
    int row=blockIdx.x,c=threadIdx.x;
    float ma=g_mpart[row],mb=g_mpart[NB+row];
    float m=fmaxf(ma,mb);
    float wa=__expf(ma-m),wb=__expf(mb-m);
    float denom=(g_lpart[row]*wa+g_lpart[NB+row]*wb)*PSCL;
    size_t o=(size_t)row*HD+c;
    float v=(g_Opart[o]*wa+g_Opart[(size_t)NB*HD+o]*wb)/denom;
    f16 h,l;splith(v,h,l);
    g_avhi[o]=h;g_avlo[o]=l;
}

// ---- atom self-attn + LN (stride 137; g_qkv stride N3P) ----
#define ATP 137
#define AT_SMEM_FLOATS (4*64*ATP+64*64+512+128)
__global__ __launch_bounds__(256,1) void atom_attn_ln_k(const float* __restrict__ xg,
    const float* __restrict__ gw,const float* __restrict__ bw){
    extern __shared__ float smf[];
    float* sx=smf;float* sq=sx+64*ATP;float* sk=sq+64*ATP;float* sv=sk+64*ATP;
    float* ss=sv+64*ATP;float* sred=ss+4096;float* srow=sred+512;
    const int tid=threadIdx.x,base=blockIdx.x*64;
    for(int idx=tid;idx<64*FDIM;idx+=256){
        int a=idx/FDIM,f=idx-a*FDIM;
        sx[a*ATP+f]=xg[(size_t)(base+a)*FDIM+f];
        size_t go=(size_t)(base+a)*N3P+f;
        sq[a*ATP+f]=g_qkv[go];sk[a*ATP+f]=g_qkv[go+FDIM];sv[a*ATP+f]=g_qkv[go+2*FDIM];
    }
    __syncthreads();
    {
        int ty=tid>>4,tx=tid&15;float acc[4][4]={};
        for(int h=0;h<FDIM;h++){
            float qv[4],kv[4];
#pragma unroll
            for(int i=0;i<4;i++){qv[i]=sq[(ty*4+i)*ATP+h];kv[i]=sk[(tx*4+i)*ATP+h];}
#pragma unroll
            for(int i=0;i<4;i++)
#pragma unroll
                for(int j=0;j<4;j++)acc[i][j]+=qv[i]*kv[j];
        }
        float scl=rsqrtf(133.0f);
#pragma unroll
        for(int i=0;i<4;i++)
#pragma unroll
            for(int j=0;j<4;j++)ss[(ty*4+i)*64+tx*4+j]=acc[i][j]*scl;
    }
    __syncthreads();
    if(tid<64){
        float mx=-1e30f;
        for(int j=0;j<64;j++)mx=fmaxf(mx,ss[tid*64+j]);
        float s=0.f;
        for(int j=0;j<64;j++){float e=__expf(ss[tid*64+j]-mx);ss[tid*64+j]=e;s+=e;}
        float inv=1.f/s;
        for(int j=0;j<64;j++)ss[tid*64+j]*=inv;
    }
    __syncthreads();
    const int r=tid>>2,qd=tid&3,f0=qd*34;
    float tv[34];
#pragma unroll
    for(int f=0;f<34;f++)tv[f]=0.f;
    for(int b=0;b<64;b++){
        float p=ss[r*64+b];const float* vb=&sv[b*ATP+f0];
#pragma unroll
        for(int f=0;f<34;f++)if(f0+f<FDIM)tv[f]+=p*vb[f];
    }
    float s1=0.f;
#pragma unroll
    for(int f=0;f<34;f++)if(f0+f<FDIM){tv[f]+=sx[r*ATP+f0+f];s1+=tv[f];}
    sred[tid]=s1;__syncthreads();
    if(qd==0)srow[r]=(sred[tid]+sred[tid+1]+sred[tid+2]+sred[tid+3])*(1.f/133.f);
    __syncthreads();
    float mu=srow[r],s2=0.f;
#pragma unroll
    for(int f=0;f<34;f++)if(f0+f<FDIM){float d=tv[f]-mu;s2+=d*d;}
    sred[tid]=s2;__syncthreads();
    if(qd==0){float var=(sred[tid]+sred[tid+1]+sred[tid+2]+sred[tid+3])*(1.f/133.f);srow[64+r]=rsqrtf(var+1e-5f);}
    __syncthreads();
    float rstd=srow[64+r];
#pragma unroll
    for(int f=0;f<34;f++){int fg=f0+f;
        if(fg<FDIM)g_fe[(size_t)(base+r)*FDIM+fg]=(tv[f]-mu)*rstd*gw[fg]+bw[fg];}
}

__global__ void gather_sum_k(const int* __restrict__ a2b){
    __shared__ int idx[MAXNB];
    int a=blockIdx.x,t=threadIdx.x;
    if(t<MAXNB)idx[t]=a2b[a*MAXNB+t];
    __syncthreads();
    float s=0.f;
#pragma unroll
    for(int j=0;j<MAXNB;j++)s+=g_msg[(size_t)idx[j]*HD+t];
    g_amsg[(size_t)a*HD+t]=s;
}
__global__ void dmpnn_fused_k(const int* __restrict__ a2b,const int* __restrict__ b2a,
    const int* __restrict__ b2revb){
    __shared__ int idx[MAXNB+1];
    __shared__ int sia;
    int b=blockIdx.x,t=threadIdx.x;
    if(t==0)sia=__ldg(&b2a[b]);
    if(t==MAXNB)idx[MAXNB]=__ldg(&b2revb[b]);
    __syncthreads();
    if(t<MAXNB)idx[t]=__ldg(&a2b[sia*MAXNB+t]);
    __syncthreads();
    float s=0.f;
#pragma unroll
    for(int j=0;j<MAXNB;j++)s+=g_msg[(size_t)idx[j]*HD+t];
    float v=s-g_msg[(size_t)idx[MAXNB]*HD+t];
    f16 h,l;splith(v,h,l);
    size_t o=(size_t)b*HD+t;
    g_tmphi[o]=h;g_tmplo[o]=l;
}
__global__ void combine_k(const float* __restrict__ wal,const float* __restrict__ walb){
    __shared__ float wred[8];
    __shared__ float salpha;
    int b=blockIdx.x,t=threadIdx.x,lane=t&31,w=t>>5;
    size_t o=(size_t)b*HD+t;
    float d=g_dmpnn[o],am=g_attm[o];
    float x=d*wal[t]+am*wal[256+t];
#pragma unroll
    for(int sft=16;sft>0;sft>>=1)x+=__shfl_xor_sync(0xffffffffu,x,sft);
    if(lane==0)wred[w]=x;
    __syncthreads();
    if(t==0){
        float s=wred[0]+wred[1]+wred[2]+wred[3]+wred[4]+wred[5]+wred[6]+wred[7];
        salpha=1.f/(1.f+__expf(-(s+walb[0])));
    }
    __syncthreads();
    float al=salpha;
    float v=fmaxf(g_inputs[o]+al*d+(1.f-al)*am,0.f);
    g_msg[o]=v;
    f16 h,l;splith(v,h,l);
    g_msghi[o]=h;g_msglo[o]=l;
}
__global__ void concat_split_k(){
    int i=blockIdx.x*blockDim.x+threadIdx.x;
    if(i>=NA*KP_WO)return;
    int row=i/KP_WO,c=i-row*KP_WO;
    float x=(c<FDIM)?g_fe[(size_t)row*FDIM+c]:(c<FDIM+HD?g_amsg[(size_t)row*HD+(c-FDIM)]:0.f);
    f16 h,l;splith(x,h,l);
    g_cathi[i]=h;g_catlo[i]=l;
}

#define MP_SMEM_FLOATS (2*64*260+4096)
__global__ __launch_bounds__(256,1) void mol_pool_k(const float* __restrict__ Wb,
    const float* __restrict__ bb,float* __restrict__ outg){
    extern __shared__ float smf[];
    float* shm=smf;float* sw=shm+64*260;float* ssc=sw+64*260;
    const int tid=threadIdx.x,base=blockIdx.x*64;
    for(int idx=tid;idx<64*HD;idx+=256){
        int a=idx>>8,c=idx&255;
        shm[a*260+c]=g_atomh[(size_t)(base+a)*HD+c];
        sw[a*260+c]=g_hmwa[(size_t)(base+a)*HD+c];
    }
    __syncthreads();
    {
        int ty=tid>>4,tx=tid&15;float acc[4][4]={};
        for(int h=0;h<HD;h++){
            float qv[4],kv[4];
#pragma unroll
            for(int i=0;i<4;i++){qv[i]=sw[(ty*4+i)*260+h];kv[i]=shm[(tx*4+i)*260+h];}
#pragma unroll
            for(int i=0;i<4;i++)
#pragma unroll
                for(int j=0;j<4;j++)acc[i][j]+=qv[i]*kv[j];
        }
#pragma unroll
        for(int i=0;i<4;i++)
#pragma unroll
            for(int j=0;j<4;j++)ssc[(ty*4+i)*64+tx*4+j]=acc[i][j];
    }
    __syncthreads();
    if(tid<64){
        float mx=-1e30f;
        for(int j=0;j<64;j++)mx=fmaxf(mx,ssc[tid*64+j]);
        float s=0.f;
        for(int j=0;j<64;j++){float e=__expf(ssc[tid*64+j]-mx);ssc[tid*64+j]=e;s+=e;}
        float inv=1.f/s;
        for(int j=0;j<64;j++)ssc[tid*64+j]*=inv;
    }
    __syncthreads();
    const int c=tid;
    float acc[64];
#pragma unroll
    for(int a=0;a<64;a++)acc[a]=0.f;
    for(int b=0;b<64;b++){
        float hv=shm[b*260+c];
#pragma unroll 16
        for(int a=0;a<64;a++)acc[a]+=ssc[a*64+b]*hv;
    }
    __syncthreads();
    for(int a=0;a<64;a++)sw[a*260+c]=acc[a];
    __syncthreads();
#pragma unroll
    for(int a=0;a<64;a++)acc[a]=0.f;
    for(int k=0;k<HD;k++){
        float wv=Wb[(size_t)k*HD+c];
#pragma unroll 16
        for(int a=0;a<64;a++)acc[a]+=sw[a*260+k]*wv;
    }
    float bv=bb[c],s=0.f;
    for(int a=0;a<64;a++){float t=fmaxf(acc[a]+bv,0.f);s+=shm[a*260+c]+t;}
    outg[(size_t)blockIdx.x*HD+c]=s*(1.f/64.f);
}

static float* symf(const void* s){void* p=nullptr;cudaGetSymbolAddress(&p,s);return (float*)p;}
static f16* symh(const void* s){void* p=nullptr;cudaGetSymbolAddress(&p,s);return (f16*)p;}

extern "C" void kernel_launch(void* const* d_in,const int* in_sizes,int n_in,void* d_out,int out_size){
    const float* f_atoms=(const float*)d_in[0];
    const float* f_bonds=(const float*)d_in[1];
    const float* Wq_atom=(const float*)d_in[2];
    const float* Wk_atom=(const float*)d_in[3];
    const float* Wv_atom=(const float*)d_in[4];
    const float* ln_g=(const float*)d_in[5];
    const float* ln_b=(const float*)d_in[6];
    const float* Wi=(const float*)d_in[7];
    const float* Wh=(const float*)d_in[8];
    const float* Wq=(const float*)d_in[9];
    const float* Wk=(const float*)d_in[10];
    const float* Wv=(const float*)d_in[11];
    const float* Wa=(const float*)d_in[12];
    const float* Walw=(const float*)d_in[13];
    const float* Walb=(const float*)d_in[14];
    const float* Wow=(const float*)d_in[15];
    const float* Wob=(const float*)d_in[16];
    const float* Wbw=(const float*)d_in[17];
    const float* Wbb=(const float*)d_in[18];
    const int* a2b=(const int*)d_in[19];
    const int* b2a=(const int*)d_in[20];
    const int* b2revb=(const int*)d_in[21];
    float* out=(float*)d_out;

    float* p_qkv=symf(g_qkv);
    float* p_inputs=symf(g_inputs);float* p_msg=symf(g_msg);
    float* p_dmpnn=symf(g_dmpnn);float* p_attm=symf(g_attm);
    float* p_atomh=symf(g_atomh);float* p_hmwa=symf(g_hmwa);
    f16* p_Q16=symh(g_Q16);f16* p_K16=symh(g_K16);f16* p_V16=symh(g_V16);
    f16* p_msghi=symh(g_msghi);f16* p_msglo=symh(g_msglo);
    f16* p_tmphi=symh(g_tmphi);f16* p_tmplo=symh(g_tmplo);
    f16* p_avhi=symh(g_avhi);f16* p_avlo=symh(g_avlo);
    f16* p_fbhi=symh(g_fbhi);f16* p_fblo=symh(g_fblo);
    f16* p_fahi=symh(g_fahi);f16* p_falo=symh(g_falo);
    f16* p_cathi=symh(g_cathi);f16* p_catlo=symh(g_catlo);
    f16* p_ahhi=symh(g_ahhi);f16* p_ahlo=symh(g_ahlo);
    f16* p_Withi=symh(g_Withi);f16* p_Witlo=symh(g_Witlo);
    f16* p_Whthi=symh(g_Whthi);f16* p_Whtlo=symh(g_Whtlo);
    f16* p_Wqkvthi=symh(g_Wqkvthi);f16* p_Wqkvtlo=symh(g_Wqkvtlo);
    f16* p_Wathi=symh(g_Wathi);f16* p_Watlo=symh(g_Watlo);
    f16* p_Wothi=symh(g_Wothi);f16* p_Wotlo=symh(g_Wotlo);
    f16* p_W3thi=symh(g_W3thi);f16* p_W3tlo=symh(g_W3tlo);

    const int AT_SMEM=AT_SMEM_FLOATS*4,MP_SMEM=MP_SMEM_FLOATS*4;
    cudaFuncSetAttribute(flash_mma,cudaFuncAttributeMaxDynamicSharedMemorySize,FL_SMEM);
    cudaFuncSetAttribute(atom_attn_ln_k,cudaFuncAttributeMaxDynamicSharedMemorySize,AT_SMEM);
    cudaFuncSetAttribute(mol_pool_k,cudaFuncAttributeMaxDynamicSharedMemorySize,MP_SMEM);
    cudaFuncSetAttribute(tgemm<1,0,0,1,1,1,0,0>,cudaFuncAttributeMaxDynamicSharedMemorySize,TG_SMEM);
    cudaFuncSetAttribute(tgemm<0,0,0,1,0,0,0,0>,cudaFuncAttributeMaxDynamicSharedMemorySize,TG_SMEM);
    cudaFuncSetAttribute(tgemm<0,0,0,0,0,0,0,1>,cudaFuncAttributeMaxDynamicSharedMemorySize,TG_SMEM);
    cudaFuncSetAttribute(tgemm<1,1,0,1,1,0,0,0>,cudaFuncAttributeMaxDynamicSharedMemorySize,TG_SMEM);

    const int WALL=SZ_WI+5*SZ_H+SZ_WO+SZ_W3;
    wsplit_all_k<<<(WALL+255)/256,256>>>(Wi,Wh,Wq,Wk,Wv,Wa,Wow,Wq_atom,Wk_atom,Wv_atom);
    asplit_k<<<(NB*KP_WI)/256,256>>>(f_bonds,p_fbhi,p_fblo,BFDIM,KP_WI);
    asplit_k<<<(NA*KP_A3)/256,256>>>(f_atoms,p_fahi,p_falo,FDIM,KP_A3);

    // atom QKV via tensor path: [4096,448] = f_atoms[4096,160] @ W3t[448,160]^T
    dim3 gq3(N3P/64,NA/128);
    tgemm<0,0,0,1,0,0,0,0><<<gq3,256,TG_SMEM>>>(p_fahi,p_falo,p_W3thi,p_W3tlo,nullptr,
        p_qkv,nullptr,nullptr,nullptr,nullptr,NA,KP_A3,N3P);
    atom_attn_ln_k<<<NMOL,256,AT_SMEM>>>(f_atoms,ln_g,ln_b);

    dim3 tgb(4,NB/128),tga(4,NA/128),tgqkv(12,NB/128);
    tgemm<1,0,0,1,1,1,0,0><<<tgb,256,TG_SMEM>>>(p_fbhi,p_fblo,p_Withi,p_Witlo,nullptr,
        p_msg,p_msghi,p_msglo,nullptr,p_inputs,NB,KP_WI,HD);

    for(int it=0;it<3;it++){
        dmpnn_fused_k<<<NB,256>>>(a2b,b2a,b2revb);
        tgemm<0,0,0,1,0,0,0,0><<<tgb,256,TG_SMEM>>>(p_tmphi,p_tmplo,p_Whthi,p_Whtlo,nullptr,
            p_dmpnn,nullptr,nullptr,nullptr,nullptr,NB,HD,HD);
        tgemm<0,0,0,0,0,0,0,1><<<tgqkv,256,TG_SMEM>>>(p_msghi,p_msglo,p_Wqkvthi,p_Wqkvtlo,nullptr,
            nullptr,p_Q16,p_K16,p_V16,nullptr,NB,HD,HD);
        flash_mma<<<dim3(NB/128,2),256,FL_SMEM>>>();
        flash_merge_k<<<NB,256>>>();
        tgemm<0,0,0,1,0,0,0,0><<<tgb,256,TG_SMEM>>>(p_avhi,p_avlo,p_Wathi,p_Watlo,nullptr,
            p_attm,nullptr,nullptr,nullptr,nullptr,NB,HD,HD);
        combine_k<<<NB,256>>>(Walw,Walb);
    }

    gather_sum_k<<<NA,256>>>(a2b);
    concat_split_k<<<(NA*KP_WO+255)/256,256>>>();
    tgemm<1,1,0,1,1,0,0,0><<<tga,256,TG_SMEM>>>(p_cathi,p_catlo,p_Wothi,p_Wotlo,Wob,
        p_atomh,p_ahhi,p_ahlo,nullptr,nullptr,NA,KP_WO,HD);
    tgemm<0,0,0,1,0,0,0,0><<<tga,256,TG_SMEM>>>(p_ahhi,p_ahlo,p_Wathi,p_Watlo,nullptr,
        p_hmwa,nullptr,nullptr,nullptr,nullptr,NA,HD,HD);
    mol_pool_k<<<NMOL,256,MP_SMEM>>>(Wbw,Wbb,out);
}